// round 4
// baseline (speedup 1.0000x reference)
#include <cuda_runtime.h>
#include <math.h>

#define NN    4096
#define INS   256
#define OUTS  64
#define MECHS 4
#define LEAKF 0.2f
#define ADJW  (NN/32)     // 128 words per row

// ---------------- scratch (device globals; no allocation allowed) ------------
__device__ float    g_pool_part[256][256];
__device__ float    g_pooled[256];
__device__ float    g_gb[512];                     // gamma[256], beta[256]
__device__ float    g_h[MECHS * NN * OUTS];        // FiLM'd features, 4 MB
__device__ float    g_esrc[MECHS * NN];
__device__ float    g_edst[MECHS * NN];
__device__ unsigned g_adjbits[NN * ADJW];          // packed adjacency, 2 MB

// ---------------- helpers ----------------------------------------------------
__device__ __forceinline__ unsigned f2tf32(float f) {
    unsigned u;
    asm("cvt.rna.tf32.f32 %0, %1;" : "=r"(u) : "f"(f));
    return u;
}

__device__ __forceinline__ void mma_tf32(float c[4],
                                         unsigned a0, unsigned a1, unsigned a2, unsigned a3,
                                         unsigned b0, unsigned b1) {
    asm volatile(
        "mma.sync.aligned.m16n8k8.row.col.f32.tf32.tf32.f32 "
        "{%0,%1,%2,%3}, {%4,%5,%6,%7}, {%8,%9}, {%0,%1,%2,%3};"
        : "+f"(c[0]), "+f"(c[1]), "+f"(c[2]), "+f"(c[3])
        : "r"(a0), "r"(a1), "r"(a2), "r"(a3), "r"(b0), "r"(b1));
}

// ---------------- 1) column-mean of x ----------------------------------------
__global__ void pool_partial_k(const float* __restrict__ x) {
    int t = threadIdx.x, b = blockIdx.x;
    int r0 = b * 16;
    float acc = 0.f;
    #pragma unroll
    for (int r = 0; r < 16; ++r) acc += x[(r0 + r) * INS + t];
    g_pool_part[b][t] = acc;
}

__global__ void pool_final_k() {
    int t = threadIdx.x;
    float acc = 0.f;
    for (int b = 0; b < 256; ++b) acc += g_pool_part[b][t];
    g_pooled[t] = acc * (1.0f / NN);
}

// ---------------- 2) conditioner ---------------------------------------------
__global__ void cond_k(const float* __restrict__ Wc, const float* __restrict__ bc) {
    __shared__ float ps[256];
    int t = threadIdx.x;
    ps[t] = g_pooled[t];
    __syncthreads();
    int c = blockIdx.x * 256 + t;
    float acc = bc[c];
    for (int i = 0; i < INS; ++i) acc = fmaf(ps[i], Wc[i * 512 + c], acc);
    g_gb[c] = acc;
}

// ---------------- 3) pack adjacency (8 words per warp, MLP=8) ----------------
__global__ void pack_adj_k(const int* __restrict__ adj) {
    int w0   = (blockIdx.x * 8 + (threadIdx.x >> 5)) * 8;
    int lane = threadIdx.x & 31;
    const int* base = adj + w0 * 32;
    int v[8];
    #pragma unroll
    for (int i = 0; i < 8; ++i) v[i] = base[i * 32 + lane];
    #pragma unroll
    for (int i = 0; i < 8; ++i) {
        unsigned msk = __ballot_sync(0xffffffffu, v[i] > 0);
        if (lane == 0) g_adjbits[w0 + i] = msk;
    }
}

// ---------------- 4) h = FiLM(x @ W[m]) + fused e_src/e_dst ------------------
__global__ void hgemm_k(const float* __restrict__ x, const float* __restrict__ W,
                        const float* __restrict__ a1, const float* __restrict__ a2) {
    __shared__ float xs[64][20];
    __shared__ float ws[16][64];
    __shared__ float es[2][64][17];   // fused esd partials

    int m  = blockIdx.x;
    int rb = blockIdx.y * 64;
    int tx = threadIdx.x, ty = threadIdx.y;
    int t  = ty * 16 + tx;

    float acc[4][4] = {};
    const float* Wm = W + m * INS * OUTS;

    for (int k0 = 0; k0 < INS; k0 += 16) {
        {
            int r = t >> 2, kq = (t & 3) * 4;
            float4 v = *(const float4*)&x[(rb + r) * INS + k0 + kq];
            *(float4*)&xs[r][kq] = v;
        }
        {
            int kk = t >> 4, oq = (t & 15) * 4;
            *(float4*)&ws[kk][oq] = *(const float4*)&Wm[(k0 + kk) * OUTS + oq];
        }
        __syncthreads();
        #pragma unroll
        for (int k = 0; k < 16; ++k) {
            float a[4];
            #pragma unroll
            for (int i = 0; i < 4; ++i) a[i] = xs[ty * 4 + i][k];
            float4 b4 = *(const float4*)&ws[k][tx * 4];
            float b[4] = {b4.x, b4.y, b4.z, b4.w};
            #pragma unroll
            for (int i = 0; i < 4; ++i)
                #pragma unroll
                for (int j = 0; j < 4; ++j)
                    acc[i][j] = fmaf(a[i], b[j], acc[i][j]);
        }
        __syncthreads();
    }

    int oc = tx * 4;
    float4 gm = *(const float4*)&g_gb[m * 64 + oc];
    float4 bt = *(const float4*)&g_gb[256 + m * 64 + oc];
    float4 av1 = *(const float4*)&a1[m * 64 + oc];
    float4 av2 = *(const float4*)&a2[m * 64 + oc];
    #pragma unroll
    for (int i = 0; i < 4; ++i) {
        int row = rb + ty * 4 + i;
        float4 hv;
        hv.x = fmaf(gm.x, acc[i][0], bt.x);
        hv.y = fmaf(gm.y, acc[i][1], bt.y);
        hv.z = fmaf(gm.z, acc[i][2], bt.z);
        hv.w = fmaf(gm.w, acc[i][3], bt.w);
        *(float4*)&g_h[(m * NN + row) * OUTS + oc] = hv;
        float sp = hv.x * av1.x + hv.y * av1.y + hv.z * av1.z + hv.w * av1.w;
        float dp = hv.x * av2.x + hv.y * av2.y + hv.z * av2.z + hv.w * av2.w;
        es[0][ty * 4 + i][tx] = sp;
        es[1][ty * 4 + i][tx] = dp;
    }
    __syncthreads();
    if (t < 128) {
        int which = t >> 6, r = t & 63;
        float s = 0.f;
        #pragma unroll
        for (int k = 0; k < 16; ++k) s += es[which][r][k];
        (which ? g_edst : g_esrc)[m * NN + rb + r] = s;
    }
}

// ---------------- 5) fused attention: tf32 mma.sync, paired-H LDS.64 ---------
// Block: 128 i-rows x 1 mech, 8 warps (16 rows each). P fragments computed in
// registers (exp+mask). H tile staged as uint2{tf32 h[j], tf32 h[j+4]} with
// row stride 68 (stride%16==4 -> qcol*4+qrow distinct per half-warp, conflict-
// free LDS.64). Denominators accumulated in fp32 + quad shfl reduce.
struct AttnSmem {
    uint2    hp[64][68];    // paired H tile (pair-base jp = (j>>3)*4 + (j&3))
    float2   dsp[64];       // paired e_dst
    unsigned adjw[512];     // 128 rows x 4 words
};

__global__ void __launch_bounds__(256) attn_k(float* __restrict__ out) {
    __shared__ AttnSmem S;

    const int t    = threadIdx.x;
    const int lane = t & 31, w = t >> 5;
    const int m    = blockIdx.y;
    const int i0   = blockIdx.x * 128;
    const int r0   = w * 16;
    const int qrow = lane >> 2;       // 0..7
    const int qcol = lane & 3;        // 0..3
    const int row1 = r0 + qrow, row2 = row1 + 8;

    const float ss1 = g_esrc[m * NN + i0 + row1];
    const float ss2 = g_esrc[m * NN + i0 + row2];

    float c[8][4];
    #pragma unroll
    for (int n = 0; n < 8; ++n)
        #pragma unroll
        for (int q = 0; q < 4; ++q) c[n][q] = 0.f;
    float den1 = 0.f, den2 = 0.f;

    const float* hbase = g_h + (size_t)m * NN * OUTS;
    const float* dbase = g_edst + m * NN;

    for (int jt = 0; jt < NN / 128; ++jt) {
        const int j0 = jt * 128;
        __syncthreads();
        {   // H tile [128 x 64] -> paired tf32 smem
            #pragma unroll
            for (int it = 0; it < 4; ++it) {
                int p  = t + 256 * it;          // 0..1023, covers 4 uint2 each
                int jp = p >> 4, o4 = (p & 15) * 4;
                int j  = 8 * (jp >> 2) + (jp & 3);
                float4 v1 = *(const float4*)(hbase + (size_t)(j0 + j)     * OUTS + o4);
                float4 v2 = *(const float4*)(hbase + (size_t)(j0 + j + 4) * OUTS + o4);
                uint4 ua = make_uint4(f2tf32(v1.x), f2tf32(v2.x), f2tf32(v1.y), f2tf32(v2.y));
                uint4 ub = make_uint4(f2tf32(v1.z), f2tf32(v2.z), f2tf32(v1.w), f2tf32(v2.w));
                *(uint4*)&S.hp[jp][o4]     = ua;
                *(uint4*)&S.hp[jp][o4 + 2] = ub;
            }
        }
        if (t < 64) {   // paired e_dst
            int j = 8 * (t >> 2) + (t & 3);
            S.dsp[t] = make_float2(dbase[j0 + j], dbase[j0 + j + 4]);
        }
        {   // adjacency words: 128 rows x 4
            #pragma unroll
            for (int it = 0; it < 2; ++it) {
                int l = t + 256 * it;
                int r = l >> 2, wq = l & 3;
                S.adjw[l] = g_adjbits[(i0 + r) * ADJW + jt * 4 + wq];
            }
        }
        __syncthreads();

        unsigned aw1 = 0, aw2 = 0;
        #pragma unroll
        for (int ks = 0; ks < 16; ++ks) {
            if ((ks & 3) == 0) {
                aw1 = S.adjw[row1 * 4 + (ks >> 2)];
                aw2 = S.adjw[row2 * 4 + (ks >> 2)];
            }
            const int p1 = (ks & 3) * 8 + qcol;   // bit pos of j in word
            const int p2 = p1 + 4;
            const float2 dd = S.dsp[ks * 4 + qcol];

            float v00 = ss1 + dd.x, v10 = ss2 + dd.x;
            float v01 = ss1 + dd.y, v11 = ss2 + dd.y;
            v00 = fmaxf(v00, LEAKF * v00); v10 = fmaxf(v10, LEAKF * v10);
            v01 = fmaxf(v01, LEAKF * v01); v11 = fmaxf(v11, LEAKF * v11);
            float e00 = __expf(v00), e10 = __expf(v10);
            float e01 = __expf(v01), e11 = __expf(v11);
            e00 = ((aw1 >> p1) & 1u) ? e00 : 0.f;
            e10 = ((aw2 >> p1) & 1u) ? e10 : 0.f;
            e01 = ((aw1 >> p2) & 1u) ? e01 : 0.f;
            e11 = ((aw2 >> p2) & 1u) ? e11 : 0.f;
            den1 += e00 + e01;
            den2 += e10 + e11;
            unsigned a0 = f2tf32(e00), a1 = f2tf32(e10);
            unsigned a2 = f2tf32(e01), a3 = f2tf32(e11);

            const uint2* hrow = S.hp[ks * 4 + qcol];
            #pragma unroll
            for (int nt = 0; nt < 8; ++nt) {
                uint2 bp = hrow[nt * 8 + qrow];
                mma_tf32(c[nt], a0, a1, a2, a3, bp.x, bp.y);
            }
        }
    }

    // reduce denominators over the quad (lanes 4*qrow + 0..3)
    den1 += __shfl_xor_sync(0xffffffffu, den1, 1);
    den1 += __shfl_xor_sync(0xffffffffu, den1, 2);
    den2 += __shfl_xor_sync(0xffffffffu, den2, 1);
    den2 += __shfl_xor_sync(0xffffffffu, den2, 2);
    float inv1 = den1 > 0.f ? 1.0f / den1 : 0.f;
    float inv2 = den2 > 0.f ? 1.0f / den2 : 0.f;

    float* ob = out + (size_t)(i0) * (MECHS * OUTS) + m * OUTS;
    #pragma unroll
    for (int nt = 0; nt < 8; ++nt) {
        int col = nt * 8 + 2 * qcol;
        float x0 = c[nt][0] * inv1, x1 = c[nt][1] * inv1;
        float y0 = c[nt][2] * inv2, y1 = c[nt][3] * inv2;
        x0 = x0 > 0.f ? x0 : expm1f(x0);
        x1 = x1 > 0.f ? x1 : expm1f(x1);
        y0 = y0 > 0.f ? y0 : expm1f(y0);
        y1 = y1 > 0.f ? y1 : expm1f(y1);
        *(float2*)&ob[(size_t)row1 * (MECHS * OUTS) + col] = make_float2(x0, x1);
        *(float2*)&ob[(size_t)row2 * (MECHS * OUTS) + col] = make_float2(y0, y1);
    }
}

// ---------------- launch ------------------------------------------------------
extern "C" void kernel_launch(void* const* d_in, const int* in_sizes, int n_in,
                              void* d_out, int out_size) {
    const float* x   = (const float*)d_in[0];
    const int*   adj = (const int*)  d_in[1];
    const float* W   = (const float*)d_in[2];
    const float* a1  = (const float*)d_in[3];
    const float* a2  = (const float*)d_in[4];
    const float* Wc  = (const float*)d_in[5];
    const float* bc  = (const float*)d_in[6];
    float* out = (float*)d_out;

    pool_partial_k<<<256, 256>>>(x);
    pool_final_k<<<1, 256>>>();
    cond_k<<<2, 256>>>(Wc, bc);
    pack_adj_k<<<NN * ADJW / 64, 256>>>(adj);
    hgemm_k<<<dim3(MECHS, NN / 64), dim3(16, 16)>>>(x, W, a1, a2);
    attn_k<<<dim3(NN / 128, MECHS), 256>>>(out);
}

// round 5
// speedup vs baseline: 1.2124x; 1.2124x over previous
#include <cuda_runtime.h>
#include <math.h>

#define NN    4096
#define INS   256
#define OUTS  64
#define MECHS 4
#define LEAKF 0.2f
#define ADJW  (NN/32)     // 128 words per row

// ---------------- scratch (device globals; no allocation allowed) ------------
__device__ float    g_pool_part[256][256];
__device__ float    g_pooled[256];
__device__ float    g_gb[512];                     // gamma[256], beta[256]
__device__ float    g_h[MECHS * NN * OUTS];        // FiLM'd features, 4 MB
__device__ float    g_esrc[MECHS * NN];
__device__ float    g_edst[MECHS * NN];
__device__ unsigned g_adjbits[NN * ADJW];          // packed adjacency, 2 MB

// ---------------- helpers ----------------------------------------------------
__device__ __forceinline__ unsigned f2tf32(float f) {
    unsigned u;
    asm("cvt.rna.tf32.f32 %0, %1;" : "=r"(u) : "f"(f));
    return u;
}

__device__ __forceinline__ void mma_tf32(float c[4],
                                         unsigned a0, unsigned a1, unsigned a2, unsigned a3,
                                         unsigned b0, unsigned b1) {
    asm volatile(
        "mma.sync.aligned.m16n8k8.row.col.f32.tf32.tf32.f32 "
        "{%0,%1,%2,%3}, {%4,%5,%6,%7}, {%8,%9}, {%0,%1,%2,%3};"
        : "+f"(c[0]), "+f"(c[1]), "+f"(c[2]), "+f"(c[3])
        : "r"(a0), "r"(a1), "r"(a2), "r"(a3), "r"(b0), "r"(b1));
}

// ---------------- 1) column-mean of x ----------------------------------------
__global__ void pool_partial_k(const float* __restrict__ x) {
    int t = threadIdx.x, b = blockIdx.x;
    int r0 = b * 16;
    float acc = 0.f;
    #pragma unroll
    for (int r = 0; r < 16; ++r) acc += x[(r0 + r) * INS + t];
    g_pool_part[b][t] = acc;
}

__global__ void pool_final_k() {
    int t = threadIdx.x;
    float acc = 0.f;
    for (int b = 0; b < 256; ++b) acc += g_pool_part[b][t];
    g_pooled[t] = acc * (1.0f / NN);
}

// ---------------- 2) conditioner ---------------------------------------------
__global__ void cond_k(const float* __restrict__ Wc, const float* __restrict__ bc) {
    __shared__ float ps[256];
    int t = threadIdx.x;
    ps[t] = g_pooled[t];
    __syncthreads();
    int c = blockIdx.x * 256 + t;
    float acc = bc[c];
    for (int i = 0; i < INS; ++i) acc = fmaf(ps[i], Wc[i * 512 + c], acc);
    g_gb[c] = acc;
}

// ---------------- 3) pack adjacency (8 words per warp, MLP=8) ----------------
__global__ void pack_adj_k(const int* __restrict__ adj) {
    int w0   = (blockIdx.x * 8 + (threadIdx.x >> 5)) * 8;
    int lane = threadIdx.x & 31;
    const int* base = adj + w0 * 32;
    int v[8];
    #pragma unroll
    for (int i = 0; i < 8; ++i) v[i] = base[i * 32 + lane];
    #pragma unroll
    for (int i = 0; i < 8; ++i) {
        unsigned msk = __ballot_sync(0xffffffffu, v[i] > 0);
        if (lane == 0) g_adjbits[w0 + i] = msk;
    }
}

// ---------------- 4) h = FiLM(x @ W[m]) + fused e_src/e_dst ------------------
__global__ void hgemm_k(const float* __restrict__ x, const float* __restrict__ W,
                        const float* __restrict__ a1, const float* __restrict__ a2) {
    __shared__ float xs[64][20];
    __shared__ float ws[16][64];
    __shared__ float es[2][64][17];   // fused esd partials

    int m  = blockIdx.x;
    int rb = blockIdx.y * 64;
    int tx = threadIdx.x, ty = threadIdx.y;
    int t  = ty * 16 + tx;

    float acc[4][4] = {};
    const float* Wm = W + m * INS * OUTS;

    for (int k0 = 0; k0 < INS; k0 += 16) {
        {
            int r = t >> 2, kq = (t & 3) * 4;
            float4 v = *(const float4*)&x[(rb + r) * INS + k0 + kq];
            *(float4*)&xs[r][kq] = v;
        }
        {
            int kk = t >> 4, oq = (t & 15) * 4;
            *(float4*)&ws[kk][oq] = *(const float4*)&Wm[(k0 + kk) * OUTS + oq];
        }
        __syncthreads();
        #pragma unroll
        for (int k = 0; k < 16; ++k) {
            float a[4];
            #pragma unroll
            for (int i = 0; i < 4; ++i) a[i] = xs[ty * 4 + i][k];
            float4 b4 = *(const float4*)&ws[k][tx * 4];
            float b[4] = {b4.x, b4.y, b4.z, b4.w};
            #pragma unroll
            for (int i = 0; i < 4; ++i)
                #pragma unroll
                for (int j = 0; j < 4; ++j)
                    acc[i][j] = fmaf(a[i], b[j], acc[i][j]);
        }
        __syncthreads();
    }

    int oc = tx * 4;
    float4 gm = *(const float4*)&g_gb[m * 64 + oc];
    float4 bt = *(const float4*)&g_gb[256 + m * 64 + oc];
    float4 av1 = *(const float4*)&a1[m * 64 + oc];
    float4 av2 = *(const float4*)&a2[m * 64 + oc];
    #pragma unroll
    for (int i = 0; i < 4; ++i) {
        int row = rb + ty * 4 + i;
        float4 hv;
        hv.x = fmaf(gm.x, acc[i][0], bt.x);
        hv.y = fmaf(gm.y, acc[i][1], bt.y);
        hv.z = fmaf(gm.z, acc[i][2], bt.z);
        hv.w = fmaf(gm.w, acc[i][3], bt.w);
        *(float4*)&g_h[(m * NN + row) * OUTS + oc] = hv;
        float sp = hv.x * av1.x + hv.y * av1.y + hv.z * av1.z + hv.w * av1.w;
        float dp = hv.x * av2.x + hv.y * av2.y + hv.z * av2.z + hv.w * av2.w;
        es[0][ty * 4 + i][tx] = sp;
        es[1][ty * 4 + i][tx] = dp;
    }
    __syncthreads();
    if (t < 128) {
        int which = t >> 6, r = t & 63;
        float s = 0.f;
        #pragma unroll
        for (int k = 0; k < 16; ++k) s += es[which][r][k];
        (which ? g_edst : g_esrc)[m * NN + rb + r] = s;
    }
}

// ---------------- 5) fused attention (Round-3 version, verbatim) -------------
// Block: 128 i-rows x 1 mech, 8 warps (16 rows each). P fragments computed in
// registers (exp+mask); H tile staged in smem as tf32 with stride 72 (bank-
// conflict-free B-frag loads). Row denominators via a ones-column MMA tile.
struct AttnSmem {
    unsigned hs[128][72];   // H tile, tf32 bits, padded stride
    float    ds[128];
    unsigned adjw[512];     // 128 rows x 4 words
};

__global__ void __launch_bounds__(256) attn_k(float* __restrict__ out) {
    __shared__ AttnSmem S;

    const int t    = threadIdx.x;
    const int lane = t & 31, w = t >> 5;
    const int m    = blockIdx.y;
    const int i0   = blockIdx.x * 128;
    const int r0   = w * 16;
    const int qrow = lane >> 2;       // 0..7
    const int qcol = lane & 3;        // 0..3
    const int row1 = r0 + qrow, row2 = row1 + 8;

    const float ss1 = g_esrc[m * NN + i0 + row1];
    const float ss2 = g_esrc[m * NN + i0 + row2];
    const unsigned bones = f2tf32(qrow == 0 ? 1.0f : 0.0f);   // ones-column frag

    float c[9][4];
    #pragma unroll
    for (int n = 0; n < 9; ++n)
        #pragma unroll
        for (int q = 0; q < 4; ++q) c[n][q] = 0.f;

    const float* hbase = g_h + (size_t)m * NN * OUTS;

    for (int jt = 0; jt < NN / 128; ++jt) {
        const int j0 = jt * 128;
        __syncthreads();
        {   // H tile [128 x 64] -> tf32 smem (stride 72)
            const float4* hsrc = (const float4*)(hbase + j0 * OUTS);
            #pragma unroll
            for (int it = 0; it < 8; ++it) {
                int f = t + 256 * it;          // float4 index
                int j = f >> 4, o4 = (f & 15) * 4;
                float4 v = hsrc[f];
                uint4 u;
                u.x = f2tf32(v.x); u.y = f2tf32(v.y);
                u.z = f2tf32(v.z); u.w = f2tf32(v.w);
                *(uint4*)&S.hs[j][o4] = u;
            }
        }
        if (t < 128) S.ds[t] = g_edst[m * NN + j0 + t];
        {   // adjacency words: 512 = 128 rows x 4
            #pragma unroll
            for (int it = 0; it < 2; ++it) {
                int l = t + 256 * it;
                int r = l >> 2, wq = l & 3;
                S.adjw[l] = g_adjbits[(i0 + r) * ADJW + jt * 4 + wq];
            }
        }
        __syncthreads();

        unsigned aw1 = 0, aw2 = 0;
        #pragma unroll
        for (int ks = 0; ks < 16; ++ks) {
            if ((ks & 3) == 0) {
                aw1 = S.adjw[row1 * 4 + (ks >> 2)];
                aw2 = S.adjw[row2 * 4 + (ks >> 2)];
            }
            const int p1 = (ks & 3) * 8 + qcol;   // bit pos of j in word
            const int p2 = p1 + 4;
            const float d1 = S.ds[8 * ks + qcol];
            const float d2 = S.ds[8 * ks + qcol + 4];

            float v00 = ss1 + d1, v10 = ss2 + d1, v01 = ss1 + d2, v11 = ss2 + d2;
            v00 = fmaxf(v00, LEAKF * v00); v10 = fmaxf(v10, LEAKF * v10);
            v01 = fmaxf(v01, LEAKF * v01); v11 = fmaxf(v11, LEAKF * v11);
            float e00 = __expf(v00), e10 = __expf(v10);
            float e01 = __expf(v01), e11 = __expf(v11);
            e00 = ((aw1 >> p1) & 1u) ? e00 : 0.f;
            e10 = ((aw2 >> p1) & 1u) ? e10 : 0.f;
            e01 = ((aw1 >> p2) & 1u) ? e01 : 0.f;
            e11 = ((aw2 >> p2) & 1u) ? e11 : 0.f;
            unsigned a0 = f2tf32(e00), a1 = f2tf32(e10);
            unsigned a2 = f2tf32(e01), a3 = f2tf32(e11);

            const int kb = 8 * ks + qcol;
            #pragma unroll
            for (int nt = 0; nt < 8; ++nt) {
                unsigned b0 = S.hs[kb][nt * 8 + qrow];
                unsigned b1 = S.hs[kb + 4][nt * 8 + qrow];
                mma_tf32(c[nt], a0, a1, a2, a3, b0, b1);
            }
            mma_tf32(c[8], a0, a1, a2, a3, bones, bones);   // row-sum tile
        }
    }

    // denominators live in col 0 of tile 8 (threads with qcol==0)
    float den1 = __shfl_sync(0xffffffffu, c[8][0], lane & ~3);
    float den2 = __shfl_sync(0xffffffffu, c[8][2], lane & ~3);
    float inv1 = den1 > 0.f ? 1.0f / den1 : 0.f;
    float inv2 = den2 > 0.f ? 1.0f / den2 : 0.f;

    float* ob = out + (size_t)(i0) * (MECHS * OUTS) + m * OUTS;
    #pragma unroll
    for (int nt = 0; nt < 8; ++nt) {
        int col = nt * 8 + 2 * qcol;
        float x0 = c[nt][0] * inv1, x1 = c[nt][1] * inv1;
        float y0 = c[nt][2] * inv2, y1 = c[nt][3] * inv2;
        x0 = x0 > 0.f ? x0 : expm1f(x0);
        x1 = x1 > 0.f ? x1 : expm1f(x1);
        y0 = y0 > 0.f ? y0 : expm1f(y0);
        y1 = y1 > 0.f ? y1 : expm1f(y1);
        *(float2*)&ob[(size_t)row1 * (MECHS * OUTS) + col] = make_float2(x0, x1);
        *(float2*)&ob[(size_t)row2 * (MECHS * OUTS) + col] = make_float2(y0, y1);
    }
}

// ---------------- launch ------------------------------------------------------
extern "C" void kernel_launch(void* const* d_in, const int* in_sizes, int n_in,
                              void* d_out, int out_size) {
    const float* x   = (const float*)d_in[0];
    const int*   adj = (const int*)  d_in[1];
    const float* W   = (const float*)d_in[2];
    const float* a1  = (const float*)d_in[3];
    const float* a2  = (const float*)d_in[4];
    const float* Wc  = (const float*)d_in[5];
    const float* bc  = (const float*)d_in[6];
    float* out = (float*)d_out;

    pool_partial_k<<<256, 256>>>(x);
    pool_final_k<<<1, 256>>>();
    cond_k<<<2, 256>>>(Wc, bc);
    pack_adj_k<<<NN * ADJW / 64, 256>>>(adj);
    hgemm_k<<<dim3(MECHS, NN / 64), dim3(16, 16)>>>(x, W, a1, a2);
    attn_k<<<dim3(NN / 128, MECHS), 256>>>(out);
}

// round 6
// speedup vs baseline: 1.3961x; 1.1515x over previous
#include <cuda_runtime.h>
#include <math.h>

#define NN    4096
#define INS   256
#define OUTS  64
#define MECHS 4
#define LEAKF 0.2f
#define LOG2E 1.4426950408889634f
#define ADJW  (NN/32)     // 128 words per row

// ---------------- scratch (device globals; no allocation allowed) ------------
__device__ float    g_pool_part[256][256];
__device__ float    g_pooled[256];
__device__ float    g_gb[512];                     // gamma[256], beta[256]
__device__ unsigned g_h[MECHS * NN * OUTS];        // FiLM'd features, tf32 bits
__device__ float    g_esrc[MECHS * NN];            // prescaled by LOG2E
__device__ float    g_edst[MECHS * NN];            // prescaled by LOG2E
__device__ unsigned g_adjbits[NN * ADJW];          // packed adjacency, 2 MB

// ---------------- helpers ----------------------------------------------------
__device__ __forceinline__ unsigned f2tf32(float f) {
    unsigned u;
    asm("cvt.rna.tf32.f32 %0, %1;" : "=r"(u) : "f"(f));
    return u;
}

__device__ __forceinline__ float ex2f(float x) {
    float r;
    asm("ex2.approx.f32 %0, %1;" : "=f"(r) : "f"(x));
    return r;
}

__device__ __forceinline__ void mma_tf32(float c[4],
                                         unsigned a0, unsigned a1, unsigned a2, unsigned a3,
                                         unsigned b0, unsigned b1) {
    asm volatile(
        "mma.sync.aligned.m16n8k8.row.col.f32.tf32.tf32.f32 "
        "{%0,%1,%2,%3}, {%4,%5,%6,%7}, {%8,%9}, {%0,%1,%2,%3};"
        : "+f"(c[0]), "+f"(c[1]), "+f"(c[2]), "+f"(c[3])
        : "r"(a0), "r"(a1), "r"(a2), "r"(a3), "r"(b0), "r"(b1));
}

__device__ __forceinline__ unsigned smaddr(const void* p) {
    return (unsigned)__cvta_generic_to_shared(p);
}

#define CPAS16(dst, src) \
    asm volatile("cp.async.cg.shared.global [%0], [%1], 16;" :: "r"(dst), "l"(src))
#define CP_COMMIT() asm volatile("cp.async.commit_group;")
#define CP_WAIT1()  asm volatile("cp.async.wait_group 1;")
#define CP_WAIT0()  asm volatile("cp.async.wait_group 0;")

// ---------------- 1) column-mean of x ----------------------------------------
__global__ void pool_partial_k(const float* __restrict__ x) {
    int t = threadIdx.x, b = blockIdx.x;
    int r0 = b * 16;
    float acc = 0.f;
    #pragma unroll
    for (int r = 0; r < 16; ++r) acc += x[(r0 + r) * INS + t];
    g_pool_part[b][t] = acc;
}

__global__ void pool_final_k() {
    int t = threadIdx.x;
    float acc = 0.f;
    for (int b = 0; b < 256; ++b) acc += g_pool_part[b][t];
    g_pooled[t] = acc * (1.0f / NN);
}

// ---------------- 2) conditioner ---------------------------------------------
__global__ void cond_k(const float* __restrict__ Wc, const float* __restrict__ bc) {
    __shared__ float ps[256];
    int t = threadIdx.x;
    ps[t] = g_pooled[t];
    __syncthreads();
    int c = blockIdx.x * 256 + t;
    float acc = bc[c];
    for (int i = 0; i < INS; ++i) acc = fmaf(ps[i], Wc[i * 512 + c], acc);
    g_gb[c] = acc;
}

// ---------------- 3) pack adjacency (8 words per warp, MLP=8) ----------------
__global__ void pack_adj_k(const int* __restrict__ adj) {
    int w0   = (blockIdx.x * 8 + (threadIdx.x >> 5)) * 8;
    int lane = threadIdx.x & 31;
    const int* base = adj + w0 * 32;
    int v[8];
    #pragma unroll
    for (int i = 0; i < 8; ++i) v[i] = base[i * 32 + lane];
    #pragma unroll
    for (int i = 0; i < 8; ++i) {
        unsigned msk = __ballot_sync(0xffffffffu, v[i] > 0);
        if (lane == 0) g_adjbits[w0 + i] = msk;
    }
}

// ---------------- 4) h = FiLM(x @ W[m]) + fused e_src/e_dst ------------------
// Stores tf32-rounded h bits (attn consumes them raw); esd uses exact h.
__global__ void hgemm_k(const float* __restrict__ x, const float* __restrict__ W,
                        const float* __restrict__ a1, const float* __restrict__ a2) {
    __shared__ float xs[64][20];
    __shared__ float ws[16][64];
    __shared__ float es[2][64][17];

    int m  = blockIdx.x;
    int rb = blockIdx.y * 64;
    int tx = threadIdx.x, ty = threadIdx.y;
    int t  = ty * 16 + tx;

    float acc[4][4] = {};
    const float* Wm = W + m * INS * OUTS;

    for (int k0 = 0; k0 < INS; k0 += 16) {
        {
            int r = t >> 2, kq = (t & 3) * 4;
            float4 v = *(const float4*)&x[(rb + r) * INS + k0 + kq];
            *(float4*)&xs[r][kq] = v;
        }
        {
            int kk = t >> 4, oq = (t & 15) * 4;
            *(float4*)&ws[kk][oq] = *(const float4*)&Wm[(k0 + kk) * OUTS + oq];
        }
        __syncthreads();
        #pragma unroll
        for (int k = 0; k < 16; ++k) {
            float a[4];
            #pragma unroll
            for (int i = 0; i < 4; ++i) a[i] = xs[ty * 4 + i][k];
            float4 b4 = *(const float4*)&ws[k][tx * 4];
            float b[4] = {b4.x, b4.y, b4.z, b4.w};
            #pragma unroll
            for (int i = 0; i < 4; ++i)
                #pragma unroll
                for (int j = 0; j < 4; ++j)
                    acc[i][j] = fmaf(a[i], b[j], acc[i][j]);
        }
        __syncthreads();
    }

    int oc = tx * 4;
    float4 gm = *(const float4*)&g_gb[m * 64 + oc];
    float4 bt = *(const float4*)&g_gb[256 + m * 64 + oc];
    float4 av1 = *(const float4*)&a1[m * 64 + oc];
    float4 av2 = *(const float4*)&a2[m * 64 + oc];
    #pragma unroll
    for (int i = 0; i < 4; ++i) {
        int row = rb + ty * 4 + i;
        float4 hv;
        hv.x = fmaf(gm.x, acc[i][0], bt.x);
        hv.y = fmaf(gm.y, acc[i][1], bt.y);
        hv.z = fmaf(gm.z, acc[i][2], bt.z);
        hv.w = fmaf(gm.w, acc[i][3], bt.w);
        uint4 hu = make_uint4(f2tf32(hv.x), f2tf32(hv.y), f2tf32(hv.z), f2tf32(hv.w));
        *(uint4*)&g_h[(m * NN + row) * OUTS + oc] = hu;
        float sp = hv.x * av1.x + hv.y * av1.y + hv.z * av1.z + hv.w * av1.w;
        float dp = hv.x * av2.x + hv.y * av2.y + hv.z * av2.z + hv.w * av2.w;
        es[0][ty * 4 + i][tx] = sp;
        es[1][ty * 4 + i][tx] = dp;
    }
    __syncthreads();
    if (t < 128) {
        int which = t >> 6, r = t & 63;
        float s = 0.f;
        #pragma unroll
        for (int k = 0; k < 16; ++k) s += es[which][r][k];
        (which ? g_edst : g_esrc)[m * NN + rb + r] = s * LOG2E;   // prescale
    }
}

// ---------------- 5) fused attention: tf32 mma, cp.async double buffer -------
// Inner compute loop is the proven Round-3 pattern (stride-72 H tile, ones-
// column denominator MMA). Staging is now cp.async (no cvt, no LDG->STS).
#define HS_WORDS (128 * 72)          // one H buffer
#define SM_DS    (2 * HS_WORDS)      // word offset of ds buffers
#define SM_ADJ   (2 * HS_WORDS + 2 * 128)
#define SM_TOTAL ((2 * HS_WORDS + 2 * 128 + 2 * 512) * 4)

extern __shared__ unsigned sm_u[];

__global__ void __launch_bounds__(256) attn_k(float* __restrict__ out) {
    const int t    = threadIdx.x;
    const int lane = t & 31, w = t >> 5;
    const int m    = blockIdx.y;
    const int i0   = blockIdx.x * 128;
    const int r0   = w * 16;
    const int qrow = lane >> 2;
    const int qcol = lane & 3;
    const int row1 = r0 + qrow, row2 = row1 + 8;

    const float ss1 = g_esrc[m * NN + i0 + row1];   // already *LOG2E
    const float ss2 = g_esrc[m * NN + i0 + row2];
    const unsigned bones = f2tf32(qrow == 0 ? 1.0f : 0.0f);

    float c[9][4];
    #pragma unroll
    for (int n = 0; n < 9; ++n)
        #pragma unroll
        for (int q = 0; q < 4; ++q) c[n][q] = 0.f;

    const unsigned* hgl = g_h + (size_t)m * NN * OUTS;
    const float*    dgl = g_edst + m * NN;

    auto issue_tile = [&](int jt, int b) {
        const int j0 = jt * 128;
        unsigned* hb = sm_u + b * HS_WORDS;
        #pragma unroll
        for (int it = 0; it < 8; ++it) {
            int f = t + 256 * it;
            int j = f >> 4, o4 = (f & 15) * 4;
            CPAS16(smaddr(&hb[j * 72 + o4]), hgl + (size_t)(j0 + j) * OUTS + o4);
        }
        if (t < 32)
            CPAS16(smaddr(sm_u + SM_DS + b * 128 + t * 4), dgl + j0 + t * 4);
        if (t < 128)
            CPAS16(smaddr(sm_u + SM_ADJ + b * 512 + t * 4),
                   &g_adjbits[(size_t)(i0 + t) * ADJW + jt * 4]);
    };

    issue_tile(0, 0);
    CP_COMMIT();

    for (int jt = 0; jt < NN / 128; ++jt) {
        const int b = jt & 1;
        if (jt < NN / 128 - 1) {
            issue_tile(jt + 1, b ^ 1);
            CP_COMMIT();
            CP_WAIT1();
        } else {
            CP_WAIT0();
        }
        __syncthreads();

        const unsigned* hs = sm_u + b * HS_WORDS;
        const float*    ds = (const float*)(sm_u + SM_DS) + b * 128;
        const unsigned* aj = sm_u + SM_ADJ + b * 512;

        unsigned aw1 = 0, aw2 = 0;
        #pragma unroll
        for (int ks = 0; ks < 16; ++ks) {
            if ((ks & 3) == 0) {
                aw1 = aj[row1 * 4 + (ks >> 2)];
                aw2 = aj[row2 * 4 + (ks >> 2)];
            }
            const int p1 = (ks & 3) * 8 + qcol;
            const int p2 = p1 + 4;
            const float d1 = ds[8 * ks + qcol];
            const float d2 = ds[8 * ks + qcol + 4];

            float v00 = ss1 + d1, v10 = ss2 + d1, v01 = ss1 + d2, v11 = ss2 + d2;
            v00 = fmaxf(v00, LEAKF * v00); v10 = fmaxf(v10, LEAKF * v10);
            v01 = fmaxf(v01, LEAKF * v01); v11 = fmaxf(v11, LEAKF * v11);
            float e00 = ex2f(v00), e10 = ex2f(v10);
            float e01 = ex2f(v01), e11 = ex2f(v11);
            e00 = ((aw1 >> p1) & 1u) ? e00 : 0.f;
            e10 = ((aw2 >> p1) & 1u) ? e10 : 0.f;
            e01 = ((aw1 >> p2) & 1u) ? e01 : 0.f;
            e11 = ((aw2 >> p2) & 1u) ? e11 : 0.f;
            unsigned a0 = f2tf32(e00), a1 = f2tf32(e10);
            unsigned a2 = f2tf32(e01), a3 = f2tf32(e11);

            const int kb = 8 * ks + qcol;
            #pragma unroll
            for (int nt = 0; nt < 8; ++nt) {
                unsigned b0 = hs[kb * 72 + nt * 8 + qrow];
                unsigned b1 = hs[(kb + 4) * 72 + nt * 8 + qrow];
                mma_tf32(c[nt], a0, a1, a2, a3, b0, b1);
            }
            mma_tf32(c[8], a0, a1, a2, a3, bones, bones);
        }
        __syncthreads();   // buffer b reused by issue at iteration jt+1
    }

    float den1 = __shfl_sync(0xffffffffu, c[8][0], lane & ~3);
    float den2 = __shfl_sync(0xffffffffu, c[8][2], lane & ~3);
    float inv1 = den1 > 0.f ? 1.0f / den1 : 0.f;
    float inv2 = den2 > 0.f ? 1.0f / den2 : 0.f;

    float* ob = out + (size_t)(i0) * (MECHS * OUTS) + m * OUTS;
    #pragma unroll
    for (int nt = 0; nt < 8; ++nt) {
        int col = nt * 8 + 2 * qcol;
        float x0 = c[nt][0] * inv1, x1 = c[nt][1] * inv1;
        float y0 = c[nt][2] * inv2, y1 = c[nt][3] * inv2;
        x0 = x0 > 0.f ? x0 : expm1f(x0);
        x1 = x1 > 0.f ? x1 : expm1f(x1);
        y0 = y0 > 0.f ? y0 : expm1f(y0);
        y1 = y1 > 0.f ? y1 : expm1f(y1);
        *(float2*)&ob[(size_t)row1 * (MECHS * OUTS) + col] = make_float2(x0, x1);
        *(float2*)&ob[(size_t)row2 * (MECHS * OUTS) + col] = make_float2(y0, y1);
    }
}

// ---------------- launch ------------------------------------------------------
extern "C" void kernel_launch(void* const* d_in, const int* in_sizes, int n_in,
                              void* d_out, int out_size) {
    const float* x   = (const float*)d_in[0];
    const int*   adj = (const int*)  d_in[1];
    const float* W   = (const float*)d_in[2];
    const float* a1  = (const float*)d_in[3];
    const float* a2  = (const float*)d_in[4];
    const float* Wc  = (const float*)d_in[5];
    const float* bc  = (const float*)d_in[6];
    float* out = (float*)d_out;

    cudaFuncSetAttribute(attn_k, cudaFuncAttributeMaxDynamicSharedMemorySize,
                         SM_TOTAL);

    pool_partial_k<<<256, 256>>>(x);
    pool_final_k<<<1, 256>>>();
    cond_k<<<2, 256>>>(Wc, bc);
    pack_adj_k<<<NN * ADJW / 64, 256>>>(adj);
    hgemm_k<<<dim3(MECHS, NN / 64), dim3(16, 16)>>>(x, W, a1, a2);
    attn_k<<<dim3(NN / 128, MECHS), 256, SM_TOTAL>>>(out);
}

// round 7
// speedup vs baseline: 1.4861x; 1.0645x over previous
#include <cuda_runtime.h>
#include <math.h>

#define NN    4096
#define INS   256
#define OUTS  64
#define MECHS 4
#define LEAKF 0.2f
#define LOG2E 1.4426950408889634f
#define ADJW  (NN/32)     // 128 words per row

// ---------------- scratch (device globals; no allocation allowed) ------------
__device__ float    g_pool_part[256][256];
__device__ float    g_pooled[256];
__device__ float    g_gb[512];                       // gamma[256], beta[256]
// H in paired tf32 layout: [m][group g=j/8][jp=0..3][o=0..63] = {h[8g+jp][o], h[8g+jp+4][o]}
__device__ uint2    g_hp[MECHS * (NN / 8) * 4 * OUTS];
__device__ float    g_esrc[MECHS * NN];              // prescaled by LOG2E
__device__ float2   g_edstp[MECHS * (NN / 8) * 4];   // paired, prescaled by LOG2E
__device__ unsigned g_adjbits[NN * ADJW];            // packed adjacency, 2 MB

// ---------------- helpers ----------------------------------------------------
__device__ __forceinline__ unsigned f2tf32(float f) {
    unsigned u;
    asm("cvt.rna.tf32.f32 %0, %1;" : "=r"(u) : "f"(f));
    return u;
}

__device__ __forceinline__ float ex2f(float x) {
    float r;
    asm("ex2.approx.f32 %0, %1;" : "=f"(r) : "f"(x));
    return r;
}

__device__ __forceinline__ void mma_tf32(float c[4],
                                         unsigned a0, unsigned a1, unsigned a2, unsigned a3,
                                         unsigned b0, unsigned b1) {
    asm volatile(
        "mma.sync.aligned.m16n8k8.row.col.f32.tf32.tf32.f32 "
        "{%0,%1,%2,%3}, {%4,%5,%6,%7}, {%8,%9}, {%0,%1,%2,%3};"
        : "+f"(c[0]), "+f"(c[1]), "+f"(c[2]), "+f"(c[3])
        : "r"(a0), "r"(a1), "r"(a2), "r"(a3), "r"(b0), "r"(b1));
}

__device__ __forceinline__ unsigned smaddr(const void* p) {
    return (unsigned)__cvta_generic_to_shared(p);
}

#define CPAS16(dst, src) \
    asm volatile("cp.async.cg.shared.global [%0], [%1], 16;" :: "r"(dst), "l"(src))
#define CP_COMMIT() asm volatile("cp.async.commit_group;")
#define CP_WAIT1()  asm volatile("cp.async.wait_group 1;")
#define CP_WAIT0()  asm volatile("cp.async.wait_group 0;")

// ---------------- 1) column-mean of x ----------------------------------------
__global__ void pool_partial_k(const float* __restrict__ x) {
    int t = threadIdx.x, b = blockIdx.x;
    int r0 = b * 16;
    float acc = 0.f;
    #pragma unroll
    for (int r = 0; r < 16; ++r) acc += x[(r0 + r) * INS + t];
    g_pool_part[b][t] = acc;
}

__global__ void pool_final_k() {
    int t = threadIdx.x;
    float acc = 0.f;
    for (int b = 0; b < 256; ++b) acc += g_pool_part[b][t];
    g_pooled[t] = acc * (1.0f / NN);
}

// ---------------- 2) conditioner ---------------------------------------------
__global__ void cond_k(const float* __restrict__ Wc, const float* __restrict__ bc) {
    __shared__ float ps[256];
    int t = threadIdx.x;
    ps[t] = g_pooled[t];
    __syncthreads();
    int c = blockIdx.x * 256 + t;
    float acc = bc[c];
    for (int i = 0; i < INS; ++i) acc = fmaf(ps[i], Wc[i * 512 + c], acc);
    g_gb[c] = acc;
}

// ---------------- 3) pack adjacency (8 words per warp, MLP=8) ----------------
__global__ void pack_adj_k(const int* __restrict__ adj) {
    int w0   = (blockIdx.x * 8 + (threadIdx.x >> 5)) * 8;
    int lane = threadIdx.x & 31;
    const int* base = adj + w0 * 32;
    int v[8];
    #pragma unroll
    for (int i = 0; i < 8; ++i) v[i] = base[i * 32 + lane];
    #pragma unroll
    for (int i = 0; i < 8; ++i) {
        unsigned msk = __ballot_sync(0xffffffffu, v[i] > 0);
        if (lane == 0) g_adjbits[w0 + i] = msk;
    }
}

// ---------------- 4) h = FiLM(x @ W[m]) + fused e_src/e_dst ------------------
// Stores tf32-rounded h bits in PAIRED layout; esd uses exact h, prescaled.
__global__ void hgemm_k(const float* __restrict__ x, const float* __restrict__ W,
                        const float* __restrict__ a1, const float* __restrict__ a2) {
    __shared__ float xs[64][20];
    __shared__ float ws[16][64];
    __shared__ float es[2][64][17];

    int m  = blockIdx.x;
    int rb = blockIdx.y * 64;
    int tx = threadIdx.x, ty = threadIdx.y;
    int t  = ty * 16 + tx;

    float acc[4][4] = {};
    const float* Wm = W + m * INS * OUTS;

    for (int k0 = 0; k0 < INS; k0 += 16) {
        {
            int r = t >> 2, kq = (t & 3) * 4;
            float4 v = *(const float4*)&x[(rb + r) * INS + k0 + kq];
            *(float4*)&xs[r][kq] = v;
        }
        {
            int kk = t >> 4, oq = (t & 15) * 4;
            *(float4*)&ws[kk][oq] = *(const float4*)&Wm[(k0 + kk) * OUTS + oq];
        }
        __syncthreads();
        #pragma unroll
        for (int k = 0; k < 16; ++k) {
            float a[4];
            #pragma unroll
            for (int i = 0; i < 4; ++i) a[i] = xs[ty * 4 + i][k];
            float4 b4 = *(const float4*)&ws[k][tx * 4];
            float b[4] = {b4.x, b4.y, b4.z, b4.w};
            #pragma unroll
            for (int i = 0; i < 4; ++i)
                #pragma unroll
                for (int j = 0; j < 4; ++j)
                    acc[i][j] = fmaf(a[i], b[j], acc[i][j]);
        }
        __syncthreads();
    }

    int oc = tx * 4;
    float4 gm = *(const float4*)&g_gb[m * 64 + oc];
    float4 bt = *(const float4*)&g_gb[256 + m * 64 + oc];
    float4 av1 = *(const float4*)&a1[m * 64 + oc];
    float4 av2 = *(const float4*)&a2[m * 64 + oc];
    unsigned* hw = (unsigned*)g_hp;
    #pragma unroll
    for (int i = 0; i < 4; ++i) {
        int row = rb + ty * 4 + i;      // global row within mech
        float4 hv;
        hv.x = fmaf(gm.x, acc[i][0], bt.x);
        hv.y = fmaf(gm.y, acc[i][1], bt.y);
        hv.z = fmaf(gm.z, acc[i][2], bt.z);
        hv.w = fmaf(gm.w, acc[i][3], bt.w);
        // paired-layout scatter: word = (((m*512+g)*4+jp)*64 + o)*2 + half
        int g = row >> 3, rr = row & 7;
        int jp = rr & 3, half = rr >> 2;
        size_t base = ((((size_t)m * 512 + g) * 4 + jp) * 64 + oc) * 2 + half;
        hw[base    ] = f2tf32(hv.x);
        hw[base + 2] = f2tf32(hv.y);
        hw[base + 4] = f2tf32(hv.z);
        hw[base + 6] = f2tf32(hv.w);
        float sp = hv.x * av1.x + hv.y * av1.y + hv.z * av1.z + hv.w * av1.w;
        float dp = hv.x * av2.x + hv.y * av2.y + hv.z * av2.z + hv.w * av2.w;
        es[0][ty * 4 + i][tx] = sp;
        es[1][ty * 4 + i][tx] = dp;
    }
    __syncthreads();
    if (t < 128) {
        int which = t >> 6, r = t & 63;
        float s = 0.f;
        #pragma unroll
        for (int k = 0; k < 16; ++k) s += es[which][r][k];
        s *= LOG2E;
        int row = rb + r;
        if (which == 0) {
            g_esrc[m * NN + row] = s;
        } else {
            int g = row >> 3, rr = row & 7;
            ((float*)g_edstp)[(((size_t)m * 512 + g) * 4 + (rr & 3)) * 2 + (rr >> 2)] = s;
        }
    }
}

// ---------------- 5) fused attention: tf32 mma, cp.async, paired LDS.64 ------
// Inner loop = proven R3/R6 fragment mapping; B-frags now single LDS.64 from
// the paired global layout (smem pair-row stride 68 uint2 -> conflict-free).
// A-frags feed raw fp32 bits (tf32 truncation); ones-MMA denominator uses the
// same truncated fragments so the truncation bias cancels in p/sum(p).
#define HP_WORDS (64 * 136)              // one H buffer: 64 pair-rows x 68 uint2
#define SM_DS    (2 * HP_WORDS)          // word offsets
#define SM_ADJ   (2 * HP_WORDS + 2 * 128)
#define SM_TOTAL ((2 * HP_WORDS + 2 * 128 + 2 * 512) * 4)

extern __shared__ unsigned sm_u[];

__global__ void __launch_bounds__(256) attn_k(float* __restrict__ out) {
    const int t    = threadIdx.x;
    const int lane = t & 31, w = t >> 5;
    const int m    = blockIdx.y;
    const int i0   = blockIdx.x * 128;
    const int r0   = w * 16;
    const int qrow = lane >> 2;
    const int qcol = lane & 3;
    const int row1 = r0 + qrow, row2 = row1 + 8;

    const float ss1 = g_esrc[m * NN + i0 + row1];   // already *LOG2E
    const float ss2 = g_esrc[m * NN + i0 + row2];
    const unsigned bones = f2tf32(qrow == 0 ? 1.0f : 0.0f);

    float c[9][4];
    #pragma unroll
    for (int n = 0; n < 9; ++n)
        #pragma unroll
        for (int q = 0; q < 4; ++q) c[n][q] = 0.f;

    const char*   hgl = (const char*)(g_hp + (size_t)m * 512 * 4 * 64);
    const float2* dgl = g_edstp + (size_t)m * 512 * 4;

    auto issue_tile = [&](int jt, int b) {
        unsigned* hb = sm_u + b * HP_WORDS;
        const char* hsrc = hgl + (size_t)jt * 4096 * 8;   // 64 pair-rows x 512B
        #pragma unroll
        for (int it = 0; it < 8; ++it) {
            int f = t + 256 * it;                 // 16B chunk id, 0..2047
            int jp = f >> 5, ch = f & 31;
            CPAS16(smaddr(&hb[jp * 136 + ch * 4]), hsrc + (size_t)f * 16);
        }
        if (t < 32)
            CPAS16(smaddr(sm_u + SM_DS + b * 128 + t * 4),
                   (const char*)(dgl + jt * 64) + t * 16);
        if (t < 128)
            CPAS16(smaddr(sm_u + SM_ADJ + b * 512 + t * 4),
                   &g_adjbits[(size_t)(i0 + t) * ADJW + jt * 4]);
    };

    issue_tile(0, 0);
    CP_COMMIT();

    for (int jt = 0; jt < NN / 128; ++jt) {
        const int b = jt & 1;
        if (jt < NN / 128 - 1) {
            issue_tile(jt + 1, b ^ 1);
            CP_COMMIT();
            CP_WAIT1();
        } else {
            CP_WAIT0();
        }
        __syncthreads();

        const unsigned* hs = sm_u + b * HP_WORDS;
        const float2*   ds = (const float2*)(sm_u + SM_DS) + b * 64;
        const unsigned* aj = sm_u + SM_ADJ + b * 512;

        unsigned aw1 = 0, aw2 = 0;
        #pragma unroll
        for (int ks = 0; ks < 16; ++ks) {
            if ((ks & 3) == 0) {
                aw1 = aj[row1 * 4 + (ks >> 2)];
                aw2 = aj[row2 * 4 + (ks >> 2)];
            }
            const int p1 = (ks & 3) * 8 + qcol;
            const int p2 = p1 + 4;
            const float2 dd = ds[ks * 4 + qcol];

            float v00 = ss1 + dd.x, v10 = ss2 + dd.x;
            float v01 = ss1 + dd.y, v11 = ss2 + dd.y;
            v00 = fmaxf(v00, LEAKF * v00); v10 = fmaxf(v10, LEAKF * v10);
            v01 = fmaxf(v01, LEAKF * v01); v11 = fmaxf(v11, LEAKF * v11);
            float e00 = ex2f(v00), e10 = ex2f(v10);
            float e01 = ex2f(v01), e11 = ex2f(v11);
            e00 = ((aw1 >> p1) & 1u) ? e00 : 0.f;
            e10 = ((aw2 >> p1) & 1u) ? e10 : 0.f;
            e01 = ((aw1 >> p2) & 1u) ? e01 : 0.f;
            e11 = ((aw2 >> p2) & 1u) ? e11 : 0.f;
            unsigned a0 = __float_as_uint(e00), a1 = __float_as_uint(e10);
            unsigned a2 = __float_as_uint(e01), a3 = __float_as_uint(e11);

            const unsigned* hrow = hs + (ks * 4 + qcol) * 136 + qrow * 2;
            #pragma unroll
            for (int nt = 0; nt < 8; ++nt) {
                uint2 bp = *(const uint2*)(hrow + nt * 16);
                mma_tf32(c[nt], a0, a1, a2, a3, bp.x, bp.y);
            }
            mma_tf32(c[8], a0, a1, a2, a3, bones, bones);
        }
        __syncthreads();   // buffer b reused by issue at iteration jt+1
    }

    float den1 = __shfl_sync(0xffffffffu, c[8][0], lane & ~3);
    float den2 = __shfl_sync(0xffffffffu, c[8][2], lane & ~3);
    float inv1 = den1 > 0.f ? 1.0f / den1 : 0.f;
    float inv2 = den2 > 0.f ? 1.0f / den2 : 0.f;

    float* ob = out + (size_t)(i0) * (MECHS * OUTS) + m * OUTS;
    #pragma unroll
    for (int nt = 0; nt < 8; ++nt) {
        int col = nt * 8 + 2 * qcol;
        float x0 = c[nt][0] * inv1, x1 = c[nt][1] * inv1;
        float y0 = c[nt][2] * inv2, y1 = c[nt][3] * inv2;
        x0 = x0 > 0.f ? x0 : expm1f(x0);
        x1 = x1 > 0.f ? x1 : expm1f(x1);
        y0 = y0 > 0.f ? y0 : expm1f(y0);
        y1 = y1 > 0.f ? y1 : expm1f(y1);
        *(float2*)&ob[(size_t)row1 * (MECHS * OUTS) + col] = make_float2(x0, x1);
        *(float2*)&ob[(size_t)row2 * (MECHS * OUTS) + col] = make_float2(y0, y1);
    }
}

// ---------------- launch ------------------------------------------------------
extern "C" void kernel_launch(void* const* d_in, const int* in_sizes, int n_in,
                              void* d_out, int out_size) {
    const float* x   = (const float*)d_in[0];
    const int*   adj = (const int*)  d_in[1];
    const float* W   = (const float*)d_in[2];
    const float* a1  = (const float*)d_in[3];
    const float* a2  = (const float*)d_in[4];
    const float* Wc  = (const float*)d_in[5];
    const float* bc  = (const float*)d_in[6];
    float* out = (float*)d_out;

    cudaFuncSetAttribute(attn_k, cudaFuncAttributeMaxDynamicSharedMemorySize,
                         SM_TOTAL);

    pool_partial_k<<<256, 256>>>(x);
    pool_final_k<<<1, 256>>>();
    cond_k<<<2, 256>>>(Wc, bc);
    pack_adj_k<<<NN * ADJW / 64, 256>>>(adj);
    hgemm_k<<<dim3(MECHS, NN / 64), dim3(16, 16)>>>(x, W, a1, a2);
    attn_k<<<dim3(NN / 128, MECHS), 256, SM_TOTAL>>>(out);
}

// round 8
// speedup vs baseline: 1.8422x; 1.2396x over previous
#include <cuda_runtime.h>
#include <math.h>

#define NN    4096
#define INS   256
#define OUTS  64
#define MECHS 4
#define LEAKF 0.2f
#define LOG2E 1.4426950408889634f
#define ADJW  (NN/32)     // 128 words per row

// ---------------- scratch (device globals; no allocation allowed) ------------
__device__ float    g_pool_part[256][256];
__device__ float    g_pooled[256];
__device__ float    g_gb[512];                       // gamma[256], beta[256]
// H as bf16 in MMA-B layout. Per (mech, jtile): 32 rows x 64 uint2 (16 KB).
//   row = g16*4 + kp  (g16 = (j%128)/16, kp = ((j%16)%8)/2)
//   uint2[n] = { bf16x2(h[j0][n], h[j0+1][n]), bf16x2(h[j0+8][n], h[j0+9][n]) }, j0 = 16*g16+2*kp
__device__ unsigned g_hb[MECHS * 32 * 4096];          // 2 MB (u32 words)
__device__ float    g_esrc[MECHS * NN];               // prescaled by LOG2E
// e_dst as float4 per (mech, tile, ks, kp): {d[j0], d[j0+1], d[j0+8], d[j0+9]}
__device__ float    g_edst4[MECHS * 32 * 32 * 4];
__device__ unsigned g_adjbits[NN * ADJW];             // packed adjacency, 2 MB

// ---------------- helpers ----------------------------------------------------
__device__ __forceinline__ unsigned bf16x2pk(float hi, float lo) {
    unsigned r;
    asm("cvt.rn.bf16x2.f32 %0, %1, %2;" : "=r"(r) : "f"(hi), "f"(lo));
    return r;
}

__device__ __forceinline__ float ex2f(float x) {
    float r;
    asm("ex2.approx.f32 %0, %1;" : "=f"(r) : "f"(x));
    return r;
}

__device__ __forceinline__ void mma_bf16(float c[4],
                                         unsigned a0, unsigned a1, unsigned a2, unsigned a3,
                                         unsigned b0, unsigned b1) {
    asm volatile(
        "mma.sync.aligned.m16n8k16.row.col.f32.bf16.bf16.f32 "
        "{%0,%1,%2,%3}, {%4,%5,%6,%7}, {%8,%9}, {%0,%1,%2,%3};"
        : "+f"(c[0]), "+f"(c[1]), "+f"(c[2]), "+f"(c[3])
        : "r"(a0), "r"(a1), "r"(a2), "r"(a3), "r"(b0), "r"(b1));
}

__device__ __forceinline__ unsigned smaddr(const void* p) {
    return (unsigned)__cvta_generic_to_shared(p);
}

#define CPAS16(dst, src) \
    asm volatile("cp.async.cg.shared.global [%0], [%1], 16;" :: "r"(dst), "l"(src))
#define CP_COMMIT() asm volatile("cp.async.commit_group;")
#define CP_WAIT1()  asm volatile("cp.async.wait_group 1;")
#define CP_WAIT0()  asm volatile("cp.async.wait_group 0;")

// ---------------- 1) column-mean of x ----------------------------------------
__global__ void pool_partial_k(const float* __restrict__ x) {
    int t = threadIdx.x, b = blockIdx.x;
    int r0 = b * 16;
    float acc = 0.f;
    #pragma unroll
    for (int r = 0; r < 16; ++r) acc += x[(r0 + r) * INS + t];
    g_pool_part[b][t] = acc;
}

__global__ void pool_final_k() {
    int t = threadIdx.x;
    float acc = 0.f;
    for (int b = 0; b < 256; ++b) acc += g_pool_part[b][t];
    g_pooled[t] = acc * (1.0f / NN);
}

// ---------------- 2) conditioner ---------------------------------------------
__global__ void cond_k(const float* __restrict__ Wc, const float* __restrict__ bc) {
    __shared__ float ps[256];
    int t = threadIdx.x;
    ps[t] = g_pooled[t];
    __syncthreads();
    int c = blockIdx.x * 256 + t;
    float acc = bc[c];
    for (int i = 0; i < INS; ++i) acc = fmaf(ps[i], Wc[i * 512 + c], acc);
    g_gb[c] = acc;
}

// ---------------- 3) pack adjacency (8 words per warp, MLP=8) ----------------
__global__ void pack_adj_k(const int* __restrict__ adj) {
    int w0   = (blockIdx.x * 8 + (threadIdx.x >> 5)) * 8;
    int lane = threadIdx.x & 31;
    const int* base = adj + w0 * 32;
    int v[8];
    #pragma unroll
    for (int i = 0; i < 8; ++i) v[i] = base[i * 32 + lane];
    #pragma unroll
    for (int i = 0; i < 8; ++i) {
        unsigned msk = __ballot_sync(0xffffffffu, v[i] > 0);
        if (lane == 0) g_adjbits[w0 + i] = msk;
    }
}

// ---------------- 4) h = FiLM(x @ W[m]) + fused e_src/e_dst ------------------
// Stores bf16-pair h in MMA-B layout; esd uses exact fp32 h, prescaled.
__global__ void hgemm_k(const float* __restrict__ x, const float* __restrict__ W,
                        const float* __restrict__ a1, const float* __restrict__ a2) {
    __shared__ float xs[64][20];
    __shared__ float ws[16][64];
    __shared__ float es[2][64][17];

    int m  = blockIdx.x;
    int rb = blockIdx.y * 64;
    int tx = threadIdx.x, ty = threadIdx.y;
    int t  = ty * 16 + tx;

    float acc[4][4] = {};
    const float* Wm = W + m * INS * OUTS;

    for (int k0 = 0; k0 < INS; k0 += 16) {
        {
            int r = t >> 2, kq = (t & 3) * 4;
            float4 v = *(const float4*)&x[(rb + r) * INS + k0 + kq];
            *(float4*)&xs[r][kq] = v;
        }
        {
            int kk = t >> 4, oq = (t & 15) * 4;
            *(float4*)&ws[kk][oq] = *(const float4*)&Wm[(k0 + kk) * OUTS + oq];
        }
        __syncthreads();
        #pragma unroll
        for (int k = 0; k < 16; ++k) {
            float a[4];
            #pragma unroll
            for (int i = 0; i < 4; ++i) a[i] = xs[ty * 4 + i][k];
            float4 b4 = *(const float4*)&ws[k][tx * 4];
            float b[4] = {b4.x, b4.y, b4.z, b4.w};
            #pragma unroll
            for (int i = 0; i < 4; ++i)
                #pragma unroll
                for (int j = 0; j < 4; ++j)
                    acc[i][j] = fmaf(a[i], b[j], acc[i][j]);
        }
        __syncthreads();
    }

    int oc = tx * 4;
    float4 gm = *(const float4*)&g_gb[m * 64 + oc];
    float4 bt = *(const float4*)&g_gb[256 + m * 64 + oc];
    float4 av1 = *(const float4*)&a1[m * 64 + oc];
    float4 av2 = *(const float4*)&a2[m * 64 + oc];
    float hv[4][4];
    #pragma unroll
    for (int i = 0; i < 4; ++i) {
        hv[i][0] = fmaf(gm.x, acc[i][0], bt.x);
        hv[i][1] = fmaf(gm.y, acc[i][1], bt.y);
        hv[i][2] = fmaf(gm.z, acc[i][2], bt.z);
        hv[i][3] = fmaf(gm.w, acc[i][3], bt.w);
        float sp = hv[i][0] * av1.x + hv[i][1] * av1.y + hv[i][2] * av1.z + hv[i][3] * av1.w;
        float dp = hv[i][0] * av2.x + hv[i][1] * av2.y + hv[i][2] * av2.z + hv[i][3] * av2.w;
        es[0][ty * 4 + i][tx] = sp;
        es[1][ty * 4 + i][tx] = dp;
    }
    // bf16-pair store: rows (j0, j0+1) pack into one bf16x2 word
    #pragma unroll
    for (int p = 0; p < 2; ++p) {
        int i = 2 * p;
        int j0 = rb + ty * 4 + i;                    // even
        int jj = j0 & 15;
        int row32 = ((j0 & 127) >> 4) * 4 + ((jj & 7) >> 1);
        int half  = jj >> 3;
        size_t base = ((size_t)m * 32 + (j0 >> 7)) * 4096 + row32 * 128 + oc * 2 + half;
        #pragma unroll
        for (int c = 0; c < 4; ++c)
            g_hb[base + 2 * c] = bf16x2pk(hv[i + 1][c], hv[i][c]);
    }
    __syncthreads();
    if (t < 128) {
        int which = t >> 6, r = t & 63;
        float s = 0.f;
        #pragma unroll
        for (int k = 0; k < 16; ++k) s += es[which][r][k];
        s *= LOG2E;
        int row = rb + r;
        if (which == 0) {
            g_esrc[m * NN + row] = s;
        } else {
            int jj = row & 15;
            int idx = ((((int)m * 32 + (row >> 7)) * 32 +
                        ((row & 127) >> 4) * 4 + ((jj & 7) >> 1)) << 2) +
                      (jj & 1) + ((jj >> 3) << 1);
            g_edst4[idx] = s;
        }
    }
}

// ---------------- 5) fused attention: bf16 m16n8k16 mma, cp.async ------------
// Inner loop = proven fragment mapping, K=16 per MMA. H in smem: 32 rows x 68
// uint2 (stride 68 -> both LDS.64 half-warp phases conflict-free). ds as
// float4 per (ks,kp) -> one LDS.128/k-step. Ones-column MMA denominator on the
// same bf16 fragments (rounding cancels in p/sum p).
#define HPW      (32 * 136)              // words per H buffer (68 uint2 rows)
#define SM_DS    (2 * HPW)               // word offsets
#define SM_ADJ   (2 * HPW + 2 * 128)
#define SM_TOTAL ((2 * HPW + 2 * 128 + 2 * 512) * 4)

extern __shared__ unsigned sm_u[];

__global__ void __launch_bounds__(256, 2) attn_k(float* __restrict__ out) {
    const int t    = threadIdx.x;
    const int lane = t & 31, w = t >> 5;
    const int m    = blockIdx.y;
    const int i0   = blockIdx.x * 128;
    const int r0   = w * 16;
    const int qrow = lane >> 2;
    const int qcol = lane & 3;
    const int row1 = r0 + qrow, row2 = row1 + 8;

    const float ss1 = g_esrc[m * NN + i0 + row1];   // already *LOG2E
    const float ss2 = g_esrc[m * NN + i0 + row2];
    const unsigned bones = (qrow == 0) ? 0x3F803F80u : 0u;   // bf16x2(1,1)

    float c[9][4];
    #pragma unroll
    for (int n = 0; n < 9; ++n)
        #pragma unroll
        for (int q = 0; q < 4; ++q) c[n][q] = 0.f;

    const char* hgl = (const char*)(g_hb + (size_t)m * 32 * 4096);
    const char* dgl = (const char*)(g_edst4 + (size_t)m * 32 * 128);

    auto issue_tile = [&](int jt, int b) {
        unsigned* hb = sm_u + b * HPW;
        const char* hsrc = hgl + (size_t)jt * 16384;
        #pragma unroll
        for (int it = 0; it < 4; ++it) {
            int f = t + 256 * it;                 // 16B chunk id, 0..1023
            int row = f >> 5, ch = f & 31;
            CPAS16(smaddr(&hb[row * 136 + ch * 4]), hsrc + (size_t)f * 16);
        }
        if (t < 32)
            CPAS16(smaddr(sm_u + SM_DS + b * 128 + t * 4), dgl + jt * 512 + t * 16);
        if (t < 128)
            CPAS16(smaddr(sm_u + SM_ADJ + b * 512 + t * 4),
                   &g_adjbits[(size_t)(i0 + t) * ADJW + jt * 4]);
    };

    issue_tile(0, 0);
    CP_COMMIT();

    for (int jt = 0; jt < NN / 128; ++jt) {
        const int b = jt & 1;
        if (jt < NN / 128 - 1) {
            issue_tile(jt + 1, b ^ 1);
            CP_COMMIT();
            CP_WAIT1();
        } else {
            CP_WAIT0();
        }
        __syncthreads();

        const unsigned* hs = sm_u + b * HPW;
        const float4*   d4 = (const float4*)(sm_u + SM_DS + b * 128);
        const unsigned* aj = sm_u + SM_ADJ + b * 512;

        unsigned aw1 = 0, aw2 = 0;
        #pragma unroll
        for (int ks = 0; ks < 8; ++ks) {
            if ((ks & 1) == 0) {
                aw1 = aj[row1 * 4 + (ks >> 1)];
                aw2 = aj[row2 * 4 + (ks >> 1)];
            }
            const int pb = (ks & 1) * 16 + 2 * qcol;   // bit base for j0
            const float4 dd = d4[ks * 4 + qcol];       // d[j0],d[j0+1],d[j0+8],d[j0+9]

            // 8 P values: rows {row1,row2} x js {j0, j0+1, j0+8, j0+9}
            float v00 = ss1 + dd.x, v01 = ss1 + dd.y, v02 = ss1 + dd.z, v03 = ss1 + dd.w;
            float v10 = ss2 + dd.x, v11 = ss2 + dd.y, v12 = ss2 + dd.z, v13 = ss2 + dd.w;
            v00 = fmaxf(v00, LEAKF * v00); v01 = fmaxf(v01, LEAKF * v01);
            v02 = fmaxf(v02, LEAKF * v02); v03 = fmaxf(v03, LEAKF * v03);
            v10 = fmaxf(v10, LEAKF * v10); v11 = fmaxf(v11, LEAKF * v11);
            v12 = fmaxf(v12, LEAKF * v12); v13 = fmaxf(v13, LEAKF * v13);
            float e00 = ex2f(v00), e01 = ex2f(v01), e02 = ex2f(v02), e03 = ex2f(v03);
            float e10 = ex2f(v10), e11 = ex2f(v11), e12 = ex2f(v12), e13 = ex2f(v13);
            e00 = ((aw1 >> pb)       & 1u) ? e00 : 0.f;
            e01 = ((aw1 >> (pb + 1)) & 1u) ? e01 : 0.f;
            e02 = ((aw1 >> (pb + 8)) & 1u) ? e02 : 0.f;
            e03 = ((aw1 >> (pb + 9)) & 1u) ? e03 : 0.f;
            e10 = ((aw2 >> pb)       & 1u) ? e10 : 0.f;
            e11 = ((aw2 >> (pb + 1)) & 1u) ? e11 : 0.f;
            e12 = ((aw2 >> (pb + 8)) & 1u) ? e12 : 0.f;
            e13 = ((aw2 >> (pb + 9)) & 1u) ? e13 : 0.f;

            unsigned a0 = bf16x2pk(e01, e00);   // row1, k0/k0+1
            unsigned a1 = bf16x2pk(e11, e10);   // row2, k0/k0+1
            unsigned a2 = bf16x2pk(e03, e02);   // row1, k0+8/+9
            unsigned a3 = bf16x2pk(e13, e12);   // row2, k0+8/+9

            const unsigned* hrow = hs + (ks * 4 + qcol) * 136 + qrow * 2;
            #pragma unroll
            for (int nt = 0; nt < 8; ++nt) {
                uint2 bp = *(const uint2*)(hrow + nt * 16);
                mma_bf16(c[nt], a0, a1, a2, a3, bp.x, bp.y);
            }
            mma_bf16(c[8], a0, a1, a2, a3, bones, bones);
        }
        __syncthreads();   // buffer b reused by issue at iteration jt+1
    }

    float den1 = __shfl_sync(0xffffffffu, c[8][0], lane & ~3);
    float den2 = __shfl_sync(0xffffffffu, c[8][2], lane & ~3);
    float inv1 = den1 > 0.f ? 1.0f / den1 : 0.f;
    float inv2 = den2 > 0.f ? 1.0f / den2 : 0.f;

    float* ob = out + (size_t)(i0) * (MECHS * OUTS) + m * OUTS;
    #pragma unroll
    for (int nt = 0; nt < 8; ++nt) {
        int col = nt * 8 + 2 * qcol;
        float x0 = c[nt][0] * inv1, x1 = c[nt][1] * inv1;
        float y0 = c[nt][2] * inv2, y1 = c[nt][3] * inv2;
        x0 = x0 > 0.f ? x0 : expm1f(x0);
        x1 = x1 > 0.f ? x1 : expm1f(x1);
        y0 = y0 > 0.f ? y0 : expm1f(y0);
        y1 = y1 > 0.f ? y1 : expm1f(y1);
        *(float2*)&ob[(size_t)row1 * (MECHS * OUTS) + col] = make_float2(x0, x1);
        *(float2*)&ob[(size_t)row2 * (MECHS * OUTS) + col] = make_float2(y0, y1);
    }
}

// ---------------- launch ------------------------------------------------------
extern "C" void kernel_launch(void* const* d_in, const int* in_sizes, int n_in,
                              void* d_out, int out_size) {
    const float* x   = (const float*)d_in[0];
    const int*   adj = (const int*)  d_in[1];
    const float* W   = (const float*)d_in[2];
    const float* a1  = (const float*)d_in[3];
    const float* a2  = (const float*)d_in[4];
    const float* Wc  = (const float*)d_in[5];
    const float* bc  = (const float*)d_in[6];
    float* out = (float*)d_out;

    cudaFuncSetAttribute(attn_k, cudaFuncAttributeMaxDynamicSharedMemorySize,
                         SM_TOTAL);

    pool_partial_k<<<256, 256>>>(x);
    pool_final_k<<<1, 256>>>();
    cond_k<<<2, 256>>>(Wc, bc);
    pack_adj_k<<<NN * ADJW / 64, 256>>>(adj);
    hgemm_k<<<dim3(MECHS, NN / 64), dim3(16, 16)>>>(x, W, a1, a2);
    attn_k<<<dim3(NN / 128, MECHS), 256, SM_TOTAL>>>(out);
}

// round 9
// speedup vs baseline: 1.8440x; 1.0009x over previous
#include <cuda_runtime.h>
#include <math.h>

#define NN    4096
#define INS   256
#define OUTS  64
#define MECHS 4
#define LEAKF 0.2f
#define LOG2E 1.4426950408889634f
#define ADJW  (NN/32)     // 128 words per row
#define JSPLIT 2

// ---------------- scratch (device globals; no allocation allowed) ------------
__device__ float    g_pool_part[256][256];
__device__ float    g_pooled[256];
__device__ float    g_gb[512];                       // gamma[256], beta[256]
// H as bf16 in MMA-B layout. Per (mech, jtile): 32 rows x 64 uint2 (16 KB).
__device__ unsigned g_hb[MECHS * 32 * 4096];          // 2 MB (u32 words)
__device__ float    g_esrc[MECHS * NN];               // prescaled by LOG2E
__device__ float    g_edst4[MECHS * 32 * 32 * 4];     // paired e_dst
__device__ unsigned g_adjbits[NN * ADJW];             // packed adjacency, 2 MB
__device__ float    g_pout[JSPLIT][NN * MECHS * OUTS];// partial numerators, 8 MB
__device__ float    g_pden[JSPLIT][MECHS * NN];       // partial denominators

// ---------------- helpers ----------------------------------------------------
__device__ __forceinline__ unsigned bf16x2pk(float hi, float lo) {
    unsigned r;
    asm("cvt.rn.bf16x2.f32 %0, %1, %2;" : "=r"(r) : "f"(hi), "f"(lo));
    return r;
}

__device__ __forceinline__ float ex2f(float x) {
    float r;
    asm("ex2.approx.f32 %0, %1;" : "=f"(r) : "f"(x));
    return r;
}

__device__ __forceinline__ void mma_bf16(float c[4],
                                         unsigned a0, unsigned a1, unsigned a2, unsigned a3,
                                         unsigned b0, unsigned b1) {
    asm volatile(
        "mma.sync.aligned.m16n8k16.row.col.f32.bf16.bf16.f32 "
        "{%0,%1,%2,%3}, {%4,%5,%6,%7}, {%8,%9}, {%0,%1,%2,%3};"
        : "+f"(c[0]), "+f"(c[1]), "+f"(c[2]), "+f"(c[3])
        : "r"(a0), "r"(a1), "r"(a2), "r"(a3), "r"(b0), "r"(b1));
}

__device__ __forceinline__ unsigned smaddr(const void* p) {
    return (unsigned)__cvta_generic_to_shared(p);
}

#define CPAS16(dst, src) \
    asm volatile("cp.async.cg.shared.global [%0], [%1], 16;" :: "r"(dst), "l"(src))
#define CP_COMMIT() asm volatile("cp.async.commit_group;")
#define CP_WAIT1()  asm volatile("cp.async.wait_group 1;")
#define CP_WAIT0()  asm volatile("cp.async.wait_group 0;")

// ---------------- 1) column-mean of x ----------------------------------------
__global__ void pool_partial_k(const float* __restrict__ x) {
    int t = threadIdx.x, b = blockIdx.x;
    int r0 = b * 16;
    float acc = 0.f;
    #pragma unroll
    for (int r = 0; r < 16; ++r) acc += x[(r0 + r) * INS + t];
    g_pool_part[b][t] = acc;
}

__global__ void pool_final_k() {
    int t = threadIdx.x;
    float acc = 0.f;
    for (int b = 0; b < 256; ++b) acc += g_pool_part[b][t];
    g_pooled[t] = acc * (1.0f / NN);
}

// ---------------- 2) conditioner ---------------------------------------------
__global__ void cond_k(const float* __restrict__ Wc, const float* __restrict__ bc) {
    __shared__ float ps[256];
    int t = threadIdx.x;
    ps[t] = g_pooled[t];
    __syncthreads();
    int c = blockIdx.x * 256 + t;
    float acc = bc[c];
    for (int i = 0; i < INS; ++i) acc = fmaf(ps[i], Wc[i * 512 + c], acc);
    g_gb[c] = acc;
}

// ---------------- 3) pack adjacency (8 words per warp, MLP=8) ----------------
__global__ void pack_adj_k(const int* __restrict__ adj) {
    int w0   = (blockIdx.x * 8 + (threadIdx.x >> 5)) * 8;
    int lane = threadIdx.x & 31;
    const int* base = adj + w0 * 32;
    int v[8];
    #pragma unroll
    for (int i = 0; i < 8; ++i) v[i] = base[i * 32 + lane];
    #pragma unroll
    for (int i = 0; i < 8; ++i) {
        unsigned msk = __ballot_sync(0xffffffffu, v[i] > 0);
        if (lane == 0) g_adjbits[w0 + i] = msk;
    }
}

// ---------------- 4) h = FiLM(x @ W[m]) + fused e_src/e_dst ------------------
__global__ void hgemm_k(const float* __restrict__ x, const float* __restrict__ W,
                        const float* __restrict__ a1, const float* __restrict__ a2) {
    __shared__ float xs[64][20];
    __shared__ float ws[16][64];
    __shared__ float es[2][64][17];

    int m  = blockIdx.x;
    int rb = blockIdx.y * 64;
    int tx = threadIdx.x, ty = threadIdx.y;
    int t  = ty * 16 + tx;

    float acc[4][4] = {};
    const float* Wm = W + m * INS * OUTS;

    for (int k0 = 0; k0 < INS; k0 += 16) {
        {
            int r = t >> 2, kq = (t & 3) * 4;
            float4 v = *(const float4*)&x[(rb + r) * INS + k0 + kq];
            *(float4*)&xs[r][kq] = v;
        }
        {
            int kk = t >> 4, oq = (t & 15) * 4;
            *(float4*)&ws[kk][oq] = *(const float4*)&Wm[(k0 + kk) * OUTS + oq];
        }
        __syncthreads();
        #pragma unroll
        for (int k = 0; k < 16; ++k) {
            float a[4];
            #pragma unroll
            for (int i = 0; i < 4; ++i) a[i] = xs[ty * 4 + i][k];
            float4 b4 = *(const float4*)&ws[k][tx * 4];
            float b[4] = {b4.x, b4.y, b4.z, b4.w};
            #pragma unroll
            for (int i = 0; i < 4; ++i)
                #pragma unroll
                for (int j = 0; j < 4; ++j)
                    acc[i][j] = fmaf(a[i], b[j], acc[i][j]);
        }
        __syncthreads();
    }

    int oc = tx * 4;
    float4 gm = *(const float4*)&g_gb[m * 64 + oc];
    float4 bt = *(const float4*)&g_gb[256 + m * 64 + oc];
    float4 av1 = *(const float4*)&a1[m * 64 + oc];
    float4 av2 = *(const float4*)&a2[m * 64 + oc];
    float hv[4][4];
    #pragma unroll
    for (int i = 0; i < 4; ++i) {
        hv[i][0] = fmaf(gm.x, acc[i][0], bt.x);
        hv[i][1] = fmaf(gm.y, acc[i][1], bt.y);
        hv[i][2] = fmaf(gm.z, acc[i][2], bt.z);
        hv[i][3] = fmaf(gm.w, acc[i][3], bt.w);
        float sp = hv[i][0] * av1.x + hv[i][1] * av1.y + hv[i][2] * av1.z + hv[i][3] * av1.w;
        float dp = hv[i][0] * av2.x + hv[i][1] * av2.y + hv[i][2] * av2.z + hv[i][3] * av2.w;
        es[0][ty * 4 + i][tx] = sp;
        es[1][ty * 4 + i][tx] = dp;
    }
    #pragma unroll
    for (int p = 0; p < 2; ++p) {
        int i = 2 * p;
        int j0 = rb + ty * 4 + i;                    // even
        int jj = j0 & 15;
        int row32 = ((j0 & 127) >> 4) * 4 + ((jj & 7) >> 1);
        int half  = jj >> 3;
        size_t base = ((size_t)m * 32 + (j0 >> 7)) * 4096 + row32 * 128 + oc * 2 + half;
        #pragma unroll
        for (int c = 0; c < 4; ++c)
            g_hb[base + 2 * c] = bf16x2pk(hv[i + 1][c], hv[i][c]);
    }
    __syncthreads();
    if (t < 128) {
        int which = t >> 6, r = t & 63;
        float s = 0.f;
        #pragma unroll
        for (int k = 0; k < 16; ++k) s += es[which][r][k];
        s *= LOG2E;
        int row = rb + r;
        if (which == 0) {
            g_esrc[m * NN + row] = s;
        } else {
            int jj = row & 15;
            int idx = ((((int)m * 32 + (row >> 7)) * 32 +
                        ((row & 127) >> 4) * 4 + ((jj & 7) >> 1)) << 2) +
                      (jj & 1) + ((jj >> 3) << 1);
            g_edst4[idx] = s;
        }
    }
}

// ---------------- 5) fused attention: bf16 mma, j-split for occupancy --------
// blockIdx.z picks a 16-tile j-half; partial numerators + denominators go to
// scratch; combine_k normalizes. Inner loop identical to Round 8.
#define HPW      (32 * 136)              // words per H buffer (68 uint2 rows)
#define SM_DS    (2 * HPW)
#define SM_ADJ   (2 * HPW + 2 * 128)
#define SM_TOTAL ((2 * HPW + 2 * 128 + 2 * 512) * 4)
#define NTILES   (NN / 128 / JSPLIT)     // 16 per block

extern __shared__ unsigned sm_u[];

__global__ void __launch_bounds__(256, 2) attn_k() {
    const int t    = threadIdx.x;
    const int lane = t & 31, w = t >> 5;
    const int m    = blockIdx.y;
    const int i0   = blockIdx.x * 128;
    const int jh   = blockIdx.z;
    const int jt0  = jh * NTILES;
    const int r0   = w * 16;
    const int qrow = lane >> 2;
    const int qcol = lane & 3;
    const int row1 = r0 + qrow, row2 = row1 + 8;

    const float ss1 = g_esrc[m * NN + i0 + row1];
    const float ss2 = g_esrc[m * NN + i0 + row2];
    const unsigned bones = (qrow == 0) ? 0x3F803F80u : 0u;   // bf16x2(1,1)

    float c[9][4];
    #pragma unroll
    for (int n = 0; n < 9; ++n)
        #pragma unroll
        for (int q = 0; q < 4; ++q) c[n][q] = 0.f;

    const char* hgl = (const char*)(g_hb + (size_t)m * 32 * 4096);
    const char* dgl = (const char*)(g_edst4 + (size_t)m * 32 * 128);

    auto issue_tile = [&](int jt, int b) {
        unsigned* hb = sm_u + b * HPW;
        const char* hsrc = hgl + (size_t)jt * 16384;
        #pragma unroll
        for (int it = 0; it < 4; ++it) {
            int f = t + 256 * it;
            int row = f >> 5, ch = f & 31;
            CPAS16(smaddr(&hb[row * 136 + ch * 4]), hsrc + (size_t)f * 16);
        }
        if (t < 32)
            CPAS16(smaddr(sm_u + SM_DS + b * 128 + t * 4), dgl + jt * 512 + t * 16);
        if (t < 128)
            CPAS16(smaddr(sm_u + SM_ADJ + b * 512 + t * 4),
                   &g_adjbits[(size_t)(i0 + t) * ADJW + jt * 4]);
    };

    issue_tile(jt0, 0);
    CP_COMMIT();

    for (int ti = 0; ti < NTILES; ++ti) {
        const int b = ti & 1;
        if (ti < NTILES - 1) {
            issue_tile(jt0 + ti + 1, b ^ 1);
            CP_COMMIT();
            CP_WAIT1();
        } else {
            CP_WAIT0();
        }
        __syncthreads();

        const unsigned* hs = sm_u + b * HPW;
        const float4*   d4 = (const float4*)(sm_u + SM_DS + b * 128);
        const unsigned* aj = sm_u + SM_ADJ + b * 512;

        unsigned aw1 = 0, aw2 = 0;
        #pragma unroll
        for (int ks = 0; ks < 8; ++ks) {
            if ((ks & 1) == 0) {
                aw1 = aj[row1 * 4 + (ks >> 1)];
                aw2 = aj[row2 * 4 + (ks >> 1)];
            }
            const int pb = (ks & 1) * 16 + 2 * qcol;
            const float4 dd = d4[ks * 4 + qcol];

            float v00 = ss1 + dd.x, v01 = ss1 + dd.y, v02 = ss1 + dd.z, v03 = ss1 + dd.w;
            float v10 = ss2 + dd.x, v11 = ss2 + dd.y, v12 = ss2 + dd.z, v13 = ss2 + dd.w;
            v00 = fmaxf(v00, LEAKF * v00); v01 = fmaxf(v01, LEAKF * v01);
            v02 = fmaxf(v02, LEAKF * v02); v03 = fmaxf(v03, LEAKF * v03);
            v10 = fmaxf(v10, LEAKF * v10); v11 = fmaxf(v11, LEAKF * v11);
            v12 = fmaxf(v12, LEAKF * v12); v13 = fmaxf(v13, LEAKF * v13);
            float e00 = ex2f(v00), e01 = ex2f(v01), e02 = ex2f(v02), e03 = ex2f(v03);
            float e10 = ex2f(v10), e11 = ex2f(v11), e12 = ex2f(v12), e13 = ex2f(v13);
            e00 = ((aw1 >> pb)       & 1u) ? e00 : 0.f;
            e01 = ((aw1 >> (pb + 1)) & 1u) ? e01 : 0.f;
            e02 = ((aw1 >> (pb + 8)) & 1u) ? e02 : 0.f;
            e03 = ((aw1 >> (pb + 9)) & 1u) ? e03 : 0.f;
            e10 = ((aw2 >> pb)       & 1u) ? e10 : 0.f;
            e11 = ((aw2 >> (pb + 1)) & 1u) ? e11 : 0.f;
            e12 = ((aw2 >> (pb + 8)) & 1u) ? e12 : 0.f;
            e13 = ((aw2 >> (pb + 9)) & 1u) ? e13 : 0.f;

            unsigned a0 = bf16x2pk(e01, e00);
            unsigned a1 = bf16x2pk(e11, e10);
            unsigned a2 = bf16x2pk(e03, e02);
            unsigned a3 = bf16x2pk(e13, e12);

            const unsigned* hrow = hs + (ks * 4 + qcol) * 136 + qrow * 2;
            #pragma unroll
            for (int nt = 0; nt < 8; ++nt) {
                uint2 bp = *(const uint2*)(hrow + nt * 16);
                mma_bf16(c[nt], a0, a1, a2, a3, bp.x, bp.y);
            }
            mma_bf16(c[8], a0, a1, a2, a3, bones, bones);
        }
        __syncthreads();
    }

    // store partial denominators (col 0 of ones tile lives at qcol==0)
    if (qcol == 0) {
        g_pden[jh][m * NN + i0 + row1] = c[8][0];
        g_pden[jh][m * NN + i0 + row2] = c[8][2];
    }

    float* ob = g_pout[jh] + (size_t)(i0) * (MECHS * OUTS) + m * OUTS;
    #pragma unroll
    for (int nt = 0; nt < 8; ++nt) {
        int col = nt * 8 + 2 * qcol;
        *(float2*)&ob[(size_t)row1 * (MECHS * OUTS) + col] = make_float2(c[nt][0], c[nt][1]);
        *(float2*)&ob[(size_t)row2 * (MECHS * OUTS) + col] = make_float2(c[nt][2], c[nt][3]);
    }
}

// ---------------- 6) combine halves: normalize + ELU -------------------------
__global__ void combine_k(float* __restrict__ out) {
    int idx = blockIdx.x * 256 + threadIdx.x;          // float4 id
    const float4* p0 = (const float4*)g_pout[0];
    const float4* p1 = (const float4*)g_pout[1];
    float4 a = p0[idx], b = p1[idx];
    int row = idx >> 6;
    int mm  = (idx & 63) >> 4;
    float d = g_pden[0][mm * NN + row] + g_pden[1][mm * NN + row];
    float inv = d > 0.f ? 1.0f / d : 0.f;
    float4 r;
    r.x = (a.x + b.x) * inv; r.y = (a.y + b.y) * inv;
    r.z = (a.z + b.z) * inv; r.w = (a.w + b.w) * inv;
    r.x = r.x > 0.f ? r.x : expm1f(r.x);
    r.y = r.y > 0.f ? r.y : expm1f(r.y);
    r.z = r.z > 0.f ? r.z : expm1f(r.z);
    r.w = r.w > 0.f ? r.w : expm1f(r.w);
    ((float4*)out)[idx] = r;
}

// ---------------- launch ------------------------------------------------------
extern "C" void kernel_launch(void* const* d_in, const int* in_sizes, int n_in,
                              void* d_out, int out_size) {
    const float* x   = (const float*)d_in[0];
    const int*   adj = (const int*)  d_in[1];
    const float* W   = (const float*)d_in[2];
    const float* a1  = (const float*)d_in[3];
    const float* a2  = (const float*)d_in[4];
    const float* Wc  = (const float*)d_in[5];
    const float* bc  = (const float*)d_in[6];
    float* out = (float*)d_out;

    cudaFuncSetAttribute(attn_k, cudaFuncAttributeMaxDynamicSharedMemorySize,
                         SM_TOTAL);

    pool_partial_k<<<256, 256>>>(x);
    pool_final_k<<<1, 256>>>();
    cond_k<<<2, 256>>>(Wc, bc);
    pack_adj_k<<<NN * ADJW / 64, 256>>>(adj);
    hgemm_k<<<dim3(MECHS, NN / 64), dim3(16, 16)>>>(x, W, a1, a2);
    attn_k<<<dim3(NN / 128, MECHS, JSPLIT), 256, SM_TOTAL>>>();
    combine_k<<<NN * MECHS * OUTS / 4 / 256, 256>>>(out);
}

// round 10
// speedup vs baseline: 1.9742x; 1.0706x over previous
#include <cuda_runtime.h>
#include <math.h>

#define NN    4096
#define INS   256
#define OUTS  64
#define MECHS 4
#define LEAKF 0.2f
#define LOG2E 1.4426950408889634f
#define ADJW  (NN/32)     // 128 words per row

// ---------------- scratch (device globals; no allocation allowed) ------------
__device__ float    g_pool_part[256][256];
__device__ float    g_pooled[256];
__device__ float    g_gb[512];                       // gamma[256], beta[256]
__device__ unsigned g_hb[MECHS * 32 * 4096];          // H bf16 MMA-B layout, 2 MB
__device__ float    g_esrc[MECHS * NN];               // prescaled by LOG2E
__device__ float    g_edst4[MECHS * 32 * 32 * 4];     // paired e_dst
__device__ unsigned g_adjbits[NN * ADJW];             // packed adjacency, 2 MB
__device__ uint2    g_wp[MECHS * 128 * 64];           // W paired-tf32, 256 KB

// ---------------- helpers ----------------------------------------------------
__device__ __forceinline__ unsigned f2tf32(float f) {
    unsigned u;
    asm("cvt.rna.tf32.f32 %0, %1;" : "=r"(u) : "f"(f));
    return u;
}

__device__ __forceinline__ unsigned bf16x2pk(float hi, float lo) {
    unsigned r;
    asm("cvt.rn.bf16x2.f32 %0, %1, %2;" : "=r"(r) : "f"(hi), "f"(lo));
    return r;
}

__device__ __forceinline__ float ex2f(float x) {
    float r;
    asm("ex2.approx.f32 %0, %1;" : "=f"(r) : "f"(x));
    return r;
}

__device__ __forceinline__ void mma_tf32(float c[4],
                                         unsigned a0, unsigned a1, unsigned a2, unsigned a3,
                                         unsigned b0, unsigned b1) {
    asm volatile(
        "mma.sync.aligned.m16n8k8.row.col.f32.tf32.tf32.f32 "
        "{%0,%1,%2,%3}, {%4,%5,%6,%7}, {%8,%9}, {%0,%1,%2,%3};"
        : "+f"(c[0]), "+f"(c[1]), "+f"(c[2]), "+f"(c[3])
        : "r"(a0), "r"(a1), "r"(a2), "r"(a3), "r"(b0), "r"(b1));
}

__device__ __forceinline__ void mma_bf16(float c[4],
                                         unsigned a0, unsigned a1, unsigned a2, unsigned a3,
                                         unsigned b0, unsigned b1) {
    asm volatile(
        "mma.sync.aligned.m16n8k16.row.col.f32.bf16.bf16.f32 "
        "{%0,%1,%2,%3}, {%4,%5,%6,%7}, {%8,%9}, {%0,%1,%2,%3};"
        : "+f"(c[0]), "+f"(c[1]), "+f"(c[2]), "+f"(c[3])
        : "r"(a0), "r"(a1), "r"(a2), "r"(a3), "r"(b0), "r"(b1));
}

__device__ __forceinline__ unsigned smaddr(const void* p) {
    return (unsigned)__cvta_generic_to_shared(p);
}

#define CPAS16(dst, src) \
    asm volatile("cp.async.cg.shared.global [%0], [%1], 16;" :: "r"(dst), "l"(src))
#define CP_COMMIT() asm volatile("cp.async.commit_group;")
#define CP_WAIT1()  asm volatile("cp.async.wait_group 1;")
#define CP_WAIT0()  asm volatile("cp.async.wait_group 0;")

// H-layout word index for (m, even row j0, col n)
__device__ __forceinline__ size_t hbword(int m, int j0, int n) {
    int jj = j0 & 15;
    int row32 = ((j0 & 127) >> 4) * 4 + ((jj & 7) >> 1);
    int half  = jj >> 3;
    return ((size_t)m * 32 + (j0 >> 7)) * 4096 + row32 * 128 + n * 2 + half;
}

__device__ __forceinline__ int edidx(int m, int row) {
    int jj = row & 15;
    return ((((int)m * 32 + (row >> 7)) * 32 +
             ((row & 127) >> 4) * 4 + ((jj & 7) >> 1)) << 2) +
           (jj & 1) + ((jj >> 3) << 1);
}

// ---------------- 1) column-mean of x ----------------------------------------
__global__ void pool_partial_k(const float* __restrict__ x) {
    int t = threadIdx.x, b = blockIdx.x;
    int r0 = b * 16;
    float acc = 0.f;
    #pragma unroll
    for (int r = 0; r < 16; ++r) acc += x[(r0 + r) * INS + t];
    g_pool_part[b][t] = acc;
}

__global__ void pool_final_k() {
    int t = threadIdx.x;
    float acc = 0.f;
    for (int b = 0; b < 256; ++b) acc += g_pool_part[b][t];
    g_pooled[t] = acc * (1.0f / NN);
}

// ---------------- 2) conditioner ---------------------------------------------
__global__ void cond_k(const float* __restrict__ Wc, const float* __restrict__ bc) {
    __shared__ float ps[256];
    int t = threadIdx.x;
    ps[t] = g_pooled[t];
    __syncthreads();
    int c = blockIdx.x * 256 + t;
    float acc = bc[c];
    for (int i = 0; i < INS; ++i) acc = fmaf(ps[i], Wc[i * 512 + c], acc);
    g_gb[c] = acc;
}

// ---------------- 2b) W -> paired tf32 ---------------------------------------
// g_wp[m][kp][n] = { tf32(W[m][k][n]), tf32(W[m][k+4][n]) }, k = 8*(kp/4)+(kp%4)
__global__ void wcvt_k(const float* __restrict__ W) {
    int idx0 = (blockIdx.x * 256 + threadIdx.x) * 4;
    #pragma unroll
    for (int i = 0; i < 4; ++i) {
        int idx = idx0 + i;                        // 0 .. 32767
        int m = idx >> 13, rem = idx & 8191;
        int kp = rem >> 6, n = rem & 63;
        int k = (kp >> 2) * 8 + (kp & 3);
        float w0 = W[((size_t)m * INS + k) * OUTS + n];
        float w1 = W[((size_t)m * INS + k + 4) * OUTS + n];
        g_wp[idx] = make_uint2(f2tf32(w0), f2tf32(w1));
    }
}

// ---------------- 3) pack adjacency (8 words per warp, MLP=8) ----------------
__global__ void pack_adj_k(const int* __restrict__ adj) {
    int w0   = (blockIdx.x * 8 + (threadIdx.x >> 5)) * 8;
    int lane = threadIdx.x & 31;
    const int* base = adj + w0 * 32;
    int v[8];
    #pragma unroll
    for (int i = 0; i < 8; ++i) v[i] = base[i * 32 + lane];
    #pragma unroll
    for (int i = 0; i < 8; ++i) {
        unsigned msk = __ballot_sync(0xffffffffu, v[i] > 0);
        if (lane == 0) g_adjbits[w0 + i] = msk;
    }
}

// ---------------- 4) h = FiLM(x @ W[m]) via tf32 MMA + fused esd -------------
// Block: 128 rows x 1 mech, 8 warps x 16 rows. K chunked by 64, double-buffered
// cp.async. A-frags: conflict-free LDS.32 from stride-68 fp32 x tile + cvt.rna.
// B-frags: paired-tf32 LDS.64 (attn-proven layout). Epilogue: exact-fp32 FiLM
// + esd; bf16-pair H store via shfl with lane+4 partner.
#define XS_WORDS (128 * 68)
#define WS_WORDS (32 * 136)
#define HG_BUF   (XS_WORDS + WS_WORDS)
#define HG_SMEM  (2 * HG_BUF * 4)

extern __shared__ unsigned sm_u[];

__global__ void __launch_bounds__(256) hgemm_k(const float* __restrict__ x,
                                               const float* __restrict__ a1,
                                               const float* __restrict__ a2) {
    const int t    = threadIdx.x;
    const int lane = t & 31, w = t >> 5;
    const int m    = blockIdx.x;
    const int rb   = blockIdx.y * 128;
    const int r0   = w * 16;
    const int qrow = lane >> 2;
    const int qcol = lane & 3;
    const int row1 = r0 + qrow, row2 = row1 + 8;

    float c[8][4];
    #pragma unroll
    for (int n = 0; n < 8; ++n)
        #pragma unroll
        for (int q = 0; q < 4; ++q) c[n][q] = 0.f;

    const char* wsrc0 = (const char*)(g_wp + (size_t)m * 128 * 64);

    auto issue_chunk = [&](int kc, int b) {
        unsigned* xb = sm_u + b * HG_BUF;
        unsigned* wb = xb + XS_WORDS;
        #pragma unroll
        for (int it = 0; it < 8; ++it) {
            int f = t + 256 * it;                 // 0..2047
            int row = f >> 4, ch = f & 15;
            CPAS16(smaddr(xb + row * 68 + ch * 4),
                   x + (size_t)(rb + row) * INS + kc * 64 + ch * 4);
        }
        #pragma unroll
        for (int it = 0; it < 4; ++it) {
            int f = t + 256 * it;                 // 0..1023
            int row = f >> 5, ch = f & 31;
            CPAS16(smaddr(wb + row * 136 + ch * 4),
                   wsrc0 + ((size_t)(kc * 32 + row) * 64) * 8 + ch * 16);
        }
    };

    issue_chunk(0, 0);
    CP_COMMIT();

    for (int kc = 0; kc < 4; ++kc) {
        const int b = kc & 1;
        if (kc < 3) {
            issue_chunk(kc + 1, b ^ 1);
            CP_COMMIT();
            CP_WAIT1();
        } else {
            CP_WAIT0();
        }
        __syncthreads();

        const float*    xf = (const float*)(sm_u + b * HG_BUF);
        const unsigned* wb = sm_u + b * HG_BUF + XS_WORDS;

        #pragma unroll
        for (int ks = 0; ks < 8; ++ks) {
            int kk = 8 * ks + qcol;
            unsigned a0 = f2tf32(xf[row1 * 68 + kk]);
            unsigned a1r = f2tf32(xf[row2 * 68 + kk]);
            unsigned a2r = f2tf32(xf[row1 * 68 + kk + 4]);
            unsigned a3 = f2tf32(xf[row2 * 68 + kk + 4]);
            const unsigned* wrow = wb + (4 * ks + qcol) * 136 + qrow * 2;
            #pragma unroll
            for (int nt = 0; nt < 8; ++nt) {
                uint2 bp = *(const uint2*)(wrow + nt * 16);
                mma_tf32(c[nt], a0, a1r, a2r, a3, bp.x, bp.y);
            }
        }
        __syncthreads();
    }

    // epilogue: FiLM (exact fp32) + esd partials + bf16-pair H store
    float sp1 = 0.f, dp1 = 0.f, sp2 = 0.f, dp2 = 0.f;
    #pragma unroll
    for (int nt = 0; nt < 8; ++nt) {
        int cl0 = nt * 8 + 2 * qcol, cl1 = cl0 + 1;
        float g0 = g_gb[m * 64 + cl0], g1 = g_gb[m * 64 + cl1];
        float b0 = g_gb[256 + m * 64 + cl0], b1 = g_gb[256 + m * 64 + cl1];
        float h10 = fmaf(g0, c[nt][0], b0);
        float h11 = fmaf(g1, c[nt][1], b1);
        float h20 = fmaf(g0, c[nt][2], b0);
        float h21 = fmaf(g1, c[nt][3], b1);
        float av10 = __ldg(&a1[m * 64 + cl0]), av11 = __ldg(&a1[m * 64 + cl1]);
        float av20 = __ldg(&a2[m * 64 + cl0]), av21 = __ldg(&a2[m * 64 + cl1]);
        sp1 += h10 * av10 + h11 * av11;
        dp1 += h10 * av20 + h11 * av21;
        sp2 += h20 * av10 + h21 * av11;
        dp2 += h20 * av20 + h21 * av21;
        // partner (row+1) values live in lane+4
        float p10 = __shfl_down_sync(0xffffffffu, h10, 4);
        float p11 = __shfl_down_sync(0xffffffffu, h11, 4);
        float p20 = __shfl_down_sync(0xffffffffu, h20, 4);
        float p21 = __shfl_down_sync(0xffffffffu, h21, 4);
        if (!(qrow & 1)) {
            int j0a = rb + row1;          // even
            int j0b = rb + row2;          // even
            g_hb[hbword(m, j0a, cl0)] = bf16x2pk(p10, h10);
            g_hb[hbword(m, j0a, cl1)] = bf16x2pk(p11, h11);
            g_hb[hbword(m, j0b, cl0)] = bf16x2pk(p20, h20);
            g_hb[hbword(m, j0b, cl1)] = bf16x2pk(p21, h21);
        }
    }
    // reduce esd over quad (qcol 0..3)
    #pragma unroll
    for (int off = 1; off <= 2; off <<= 1) {
        sp1 += __shfl_xor_sync(0xffffffffu, sp1, off);
        dp1 += __shfl_xor_sync(0xffffffffu, dp1, off);
        sp2 += __shfl_xor_sync(0xffffffffu, sp2, off);
        dp2 += __shfl_xor_sync(0xffffffffu, dp2, off);
    }
    if (qcol == 0) {
        g_esrc[m * NN + rb + row1] = sp1 * LOG2E;
        g_esrc[m * NN + rb + row2] = sp2 * LOG2E;
        g_edst4[edidx(m, rb + row1)] = dp1 * LOG2E;
        g_edst4[edidx(m, rb + row2)] = dp2 * LOG2E;
    }
}

// ---------------- 5) fused attention: bf16 mma (Round-8 proven) --------------
#define HPW      (32 * 136)              // words per H buffer (68 uint2 rows)
#define SM_DS    (2 * HPW)
#define SM_ADJ   (2 * HPW + 2 * 128)
#define SM_TOTAL ((2 * HPW + 2 * 128 + 2 * 512) * 4)

__global__ void __launch_bounds__(256, 2) attn_k(float* __restrict__ out) {
    const int t    = threadIdx.x;
    const int lane = t & 31, w = t >> 5;
    const int m    = blockIdx.y;
    const int i0   = blockIdx.x * 128;
    const int r0   = w * 16;
    const int qrow = lane >> 2;
    const int qcol = lane & 3;
    const int row1 = r0 + qrow, row2 = row1 + 8;

    const float ss1 = g_esrc[m * NN + i0 + row1];
    const float ss2 = g_esrc[m * NN + i0 + row2];
    const unsigned bones = (qrow == 0) ? 0x3F803F80u : 0u;   // bf16x2(1,1)

    float c[9][4];
    #pragma unroll
    for (int n = 0; n < 9; ++n)
        #pragma unroll
        for (int q = 0; q < 4; ++q) c[n][q] = 0.f;

    const char* hgl = (const char*)(g_hb + (size_t)m * 32 * 4096);
    const char* dgl = (const char*)(g_edst4 + (size_t)m * 32 * 128);

    auto issue_tile = [&](int jt, int b) {
        unsigned* hb = sm_u + b * HPW;
        const char* hsrc = hgl + (size_t)jt * 16384;
        #pragma unroll
        for (int it = 0; it < 4; ++it) {
            int f = t + 256 * it;
            int row = f >> 5, ch = f & 31;
            CPAS16(smaddr(&hb[row * 136 + ch * 4]), hsrc + (size_t)f * 16);
        }
        if (t < 32)
            CPAS16(smaddr(sm_u + SM_DS + b * 128 + t * 4), dgl + jt * 512 + t * 16);
        if (t < 128)
            CPAS16(smaddr(sm_u + SM_ADJ + b * 512 + t * 4),
                   &g_adjbits[(size_t)(i0 + t) * ADJW + jt * 4]);
    };

    issue_tile(0, 0);
    CP_COMMIT();

    for (int jt = 0; jt < NN / 128; ++jt) {
        const int b = jt & 1;
        if (jt < NN / 128 - 1) {
            issue_tile(jt + 1, b ^ 1);
            CP_COMMIT();
            CP_WAIT1();
        } else {
            CP_WAIT0();
        }
        __syncthreads();

        const unsigned* hs = sm_u + b * HPW;
        const float4*   d4 = (const float4*)(sm_u + SM_DS + b * 128);
        const unsigned* aj = sm_u + SM_ADJ + b * 512;

        unsigned aw1 = 0, aw2 = 0;
        #pragma unroll
        for (int ks = 0; ks < 8; ++ks) {
            if ((ks & 1) == 0) {
                aw1 = aj[row1 * 4 + (ks >> 1)];
                aw2 = aj[row2 * 4 + (ks >> 1)];
            }
            const int pb = (ks & 1) * 16 + 2 * qcol;
            const float4 dd = d4[ks * 4 + qcol];

            float v00 = ss1 + dd.x, v01 = ss1 + dd.y, v02 = ss1 + dd.z, v03 = ss1 + dd.w;
            float v10 = ss2 + dd.x, v11 = ss2 + dd.y, v12 = ss2 + dd.z, v13 = ss2 + dd.w;
            v00 = fmaxf(v00, LEAKF * v00); v01 = fmaxf(v01, LEAKF * v01);
            v02 = fmaxf(v02, LEAKF * v02); v03 = fmaxf(v03, LEAKF * v03);
            v10 = fmaxf(v10, LEAKF * v10); v11 = fmaxf(v11, LEAKF * v11);
            v12 = fmaxf(v12, LEAKF * v12); v13 = fmaxf(v13, LEAKF * v13);
            float e00 = ex2f(v00), e01 = ex2f(v01), e02 = ex2f(v02), e03 = ex2f(v03);
            float e10 = ex2f(v10), e11 = ex2f(v11), e12 = ex2f(v12), e13 = ex2f(v13);
            e00 = ((aw1 >> pb)       & 1u) ? e00 : 0.f;
            e01 = ((aw1 >> (pb + 1)) & 1u) ? e01 : 0.f;
            e02 = ((aw1 >> (pb + 8)) & 1u) ? e02 : 0.f;
            e03 = ((aw1 >> (pb + 9)) & 1u) ? e03 : 0.f;
            e10 = ((aw2 >> pb)       & 1u) ? e10 : 0.f;
            e11 = ((aw2 >> (pb + 1)) & 1u) ? e11 : 0.f;
            e12 = ((aw2 >> (pb + 8)) & 1u) ? e12 : 0.f;
            e13 = ((aw2 >> (pb + 9)) & 1u) ? e13 : 0.f;

            unsigned a0 = bf16x2pk(e01, e00);
            unsigned a1 = bf16x2pk(e11, e10);
            unsigned a2 = bf16x2pk(e03, e02);
            unsigned a3 = bf16x2pk(e13, e12);

            const unsigned* hrow = hs + (ks * 4 + qcol) * 136 + qrow * 2;
            #pragma unroll
            for (int nt = 0; nt < 8; ++nt) {
                uint2 bp = *(const uint2*)(hrow + nt * 16);
                mma_bf16(c[nt], a0, a1, a2, a3, bp.x, bp.y);
            }
            mma_bf16(c[8], a0, a1, a2, a3, bones, bones);
        }
        __syncthreads();
    }

    float den1 = __shfl_sync(0xffffffffu, c[8][0], lane & ~3);
    float den2 = __shfl_sync(0xffffffffu, c[8][2], lane & ~3);
    float inv1 = den1 > 0.f ? 1.0f / den1 : 0.f;
    float inv2 = den2 > 0.f ? 1.0f / den2 : 0.f;

    float* ob = out + (size_t)(i0) * (MECHS * OUTS) + m * OUTS;
    #pragma unroll
    for (int nt = 0; nt < 8; ++nt) {
        int col = nt * 8 + 2 * qcol;
        float x0 = c[nt][0] * inv1, x1 = c[nt][1] * inv1;
        float y0 = c[nt][2] * inv2, y1 = c[nt][3] * inv2;
        x0 = x0 > 0.f ? x0 : expm1f(x0);
        x1 = x1 > 0.f ? x1 : expm1f(x1);
        y0 = y0 > 0.f ? y0 : expm1f(y0);
        y1 = y1 > 0.f ? y1 : expm1f(y1);
        *(float2*)&ob[(size_t)row1 * (MECHS * OUTS) + col] = make_float2(x0, x1);
        *(float2*)&ob[(size_t)row2 * (MECHS * OUTS) + col] = make_float2(y0, y1);
    }
}

// ---------------- launch ------------------------------------------------------
extern "C" void kernel_launch(void* const* d_in, const int* in_sizes, int n_in,
                              void* d_out, int out_size) {
    const float* x   = (const float*)d_in[0];
    const int*   adj = (const int*)  d_in[1];
    const float* W   = (const float*)d_in[2];
    const float* a1  = (const float*)d_in[3];
    const float* a2  = (const float*)d_in[4];
    const float* Wc  = (const float*)d_in[5];
    const float* bc  = (const float*)d_in[6];
    float* out = (float*)d_out;

    cudaFuncSetAttribute(attn_k, cudaFuncAttributeMaxDynamicSharedMemorySize,
                         SM_TOTAL);
    cudaFuncSetAttribute(hgemm_k, cudaFuncAttributeMaxDynamicSharedMemorySize,
                         HG_SMEM);

    pool_partial_k<<<256, 256>>>(x);
    pool_final_k<<<1, 256>>>();
    cond_k<<<2, 256>>>(Wc, bc);
    wcvt_k<<<32, 256>>>(W);
    pack_adj_k<<<NN * ADJW / 64, 256>>>(adj);
    hgemm_k<<<dim3(MECHS, NN / 128), 256, HG_SMEM>>>(x, a1, a2);
    attn_k<<<dim3(NN / 128, MECHS), 256, SM_TOTAL>>>(out);
}